// round 2
// baseline (speedup 1.0000x reference)
#include <cuda_runtime.h>
#include <cuda_fp16.h>
#include <cstdint>

// ---------------------------------------------------------------------------
// QGroupLinear: y = x @ (qw*sw)^T + bias   (fp32 in/out)
//   x [4096,4096] fp32, qw [11008,4096] int32 (int8 range),
//   sw [11008,32] fp32 (group 128), bias [11008] fp32 -> out [4096,11008] fp32
//
// Build target is plain sm_103 (no 'a' features): tcgen05.ld/st unavailable,
// so use classic mma.sync (HMMA) with cp.async multistage pipeline.
// Prep kernels dequantize to fp16 scratch (rel err ~3e-4 << 1e-3 gate).
// ---------------------------------------------------------------------------

#define M_TOTAL 4096
#define N_TOTAL 11008
#define K_TOTAL 4096

#define BM 128
#define BN 256
#define BK 32
#define STAGES 4
#define KT (K_TOTAL / BK)          // 128
#define TILES_M (M_TOTAL / BM)     // 32
#define TILES_N (N_TOTAL / BN)     // 43

#define PITCH 40                    // halfs per smem row (80 B) -> conflict-free ldmatrix
#define A_SM_BYTES (BM * PITCH * 2) // 10240
#define B_SM_BYTES (BN * PITCH * 2) // 20480
#define STAGE_BYTES (A_SM_BYTES + B_SM_BYTES)          // 30720
#define SMEM_TOTAL (STAGES * STAGE_BYTES)              // 122880

__device__ __half d_X16[16777216];   // 32 MB  (4096*4096)
__device__ __half d_W16[45088768];   // 90 MB  (11008*4096)

// ---------------------------------------------------------------------------
__device__ __forceinline__ uint32_t smem_u32(const void* p) {
    uint32_t a;
    asm("{ .reg .u64 t; cvta.to.shared.u64 t, %1; cvt.u32.u64 %0, t; }"
        : "=r"(a) : "l"(p));
    return a;
}

__device__ __forceinline__ void cp_async16(uint32_t dst, const void* src) {
    asm volatile("cp.async.cg.shared.global [%0], [%1], 16;"
                 :: "r"(dst), "l"(__cvta_generic_to_global(src)) : "memory");
}
#define CP_COMMIT() asm volatile("cp.async.commit_group;" ::: "memory")
#define CP_WAIT(n)  asm volatile("cp.async.wait_group %0;" :: "n"(n) : "memory")

__device__ __forceinline__ void ldsm4(uint32_t* r, uint32_t addr) {
    asm volatile("ldmatrix.sync.aligned.m8n8.x4.shared.b16 {%0,%1,%2,%3}, [%4];"
                 : "=r"(r[0]), "=r"(r[1]), "=r"(r[2]), "=r"(r[3]) : "r"(addr));
}

__device__ __forceinline__ void mma16816(float* c, const uint32_t* a,
                                         uint32_t b0, uint32_t b1) {
    asm volatile(
        "mma.sync.aligned.m16n8k16.row.col.f32.f16.f16.f32 "
        "{%0,%1,%2,%3}, {%4,%5,%6,%7}, {%8,%9}, {%0,%1,%2,%3};"
        : "+f"(c[0]), "+f"(c[1]), "+f"(c[2]), "+f"(c[3])
        : "r"(a[0]), "r"(a[1]), "r"(a[2]), "r"(a[3]), "r"(b0), "r"(b1));
}

// ---------------------------------------------------------------------------
// Prep kernels: dequant/convert to plain row-major fp16
// ---------------------------------------------------------------------------
__global__ void __launch_bounds__(256) prep_x_kernel(const float* __restrict__ x) {
    int idx = blockIdx.x * blockDim.x + threadIdx.x;      // 1 thread per 4 elems
    size_t base = (size_t)idx * 4;
    float4 v = *(const float4*)(x + base);
    __half2 h01 = __floats2half2_rn(v.x, v.y);
    __half2 h23 = __floats2half2_rn(v.z, v.w);
    uint2 pk;
    pk.x = *(uint32_t*)&h01;
    pk.y = *(uint32_t*)&h23;
    *(uint2*)(d_X16 + base) = pk;
}

__global__ void __launch_bounds__(256) prep_w_kernel(const int* __restrict__ qw,
                                                     const float* __restrict__ sw) {
    int idx = blockIdx.x * blockDim.x + threadIdx.x;      // 1 thread per 4 elems
    int n = idx >> 10;                                    // K/4 = 1024 per row
    int k0 = (idx & 1023) << 2;
    int4 q = *(const int4*)(qw + (size_t)n * K_TOTAL + k0);
    float s = sw[n * 32 + (k0 >> 7)];
    __half2 h01 = __floats2half2_rn((float)q.x * s, (float)q.y * s);
    __half2 h23 = __floats2half2_rn((float)q.z * s, (float)q.w * s);
    uint2 pk;
    pk.x = *(uint32_t*)&h01;
    pk.y = *(uint32_t*)&h23;
    *(uint2*)(d_W16 + (size_t)n * K_TOTAL + k0) = pk;
}

// ---------------------------------------------------------------------------
// GEMM: 256 threads, 8 warps as 2(m) x 4(n), warp tile 64x64.
// ---------------------------------------------------------------------------
__global__ void __launch_bounds__(256, 1) qgl_gemm_kernel(const float* __restrict__ bias,
                                                          float* __restrict__ out) {
    extern __shared__ char smem[];
    uint32_t sb = smem_u32(smem);
    int tid = threadIdx.x;
    int lane = tid & 31;
    int wid = tid >> 5;
    int warp_m = wid & 1;
    int warp_n = wid >> 1;
    int m_off = warp_m * 64;
    int n_off = warp_n * 64;

    // grouped-M tile swizzle for L2 locality (8 m-tiles per group)
    int bid = blockIdx.x;
    int group = bid / (8 * TILES_N);
    int rem = bid - group * (8 * TILES_N);
    int m_tile = group * 8 + (rem & 7);
    int n_tile = rem >> 3;

    const __half* xg = d_X16 + (size_t)(m_tile * BM) * K_TOTAL;
    const __half* wg = d_W16 + (size_t)(n_tile * BN) * K_TOTAL;

    // per-thread cp.async chunk coords (16B chunks, 4 per 64B k-row)
    // A: 512 chunks -> 2/thread ; B: 1024 chunks -> 4/thread
    int ca_row0 = tid >> 2, ca_col = (tid & 3) * 8;       // col in halfs

    // ldmatrix per-lane base addresses
    uint32_t aBase = sb + (uint32_t)((m_off + (lane & 15)) * PITCH + ((lane >> 4) << 3)) * 2;
    int rowB = (lane & 7) | ((lane & 16) >> 1);
    uint32_t bBase = sb + A_SM_BYTES
                   + (uint32_t)((n_off + rowB) * PITCH + (((lane >> 3) & 1) << 3)) * 2;

    float acc[4][8][4];
    #pragma unroll
    for (int mi = 0; mi < 4; mi++)
        #pragma unroll
        for (int nj = 0; nj < 8; nj++)
            #pragma unroll
            for (int r = 0; r < 4; r++) acc[mi][nj][r] = 0.0f;

    // ---- stage loader ----
    auto load_stage = [&](int s, int kt) {
        uint32_t as = sb + s * STAGE_BYTES;
        uint32_t bs = as + A_SM_BYTES;
        int k0 = kt * BK;
        #pragma unroll
        for (int i = 0; i < 2; i++) {
            int row = ca_row0 + i * 64;
            cp_async16(as + (uint32_t)(row * PITCH + ca_col) * 2,
                       xg + (size_t)row * K_TOTAL + k0 + ca_col);
        }
        #pragma unroll
        for (int i = 0; i < 4; i++) {
            int row = ca_row0 + i * 64;
            cp_async16(bs + (uint32_t)(row * PITCH + ca_col) * 2,
                       wg + (size_t)row * K_TOTAL + k0 + ca_col);
        }
    };

    // prologue: stages 0..2
    #pragma unroll
    for (int s = 0; s < STAGES - 1; s++) {
        load_stage(s, s);
        CP_COMMIT();
    }

    for (int kt = 0; kt < KT; kt++) {
        int lt = kt + STAGES - 1;
        if (lt < KT) load_stage(lt & (STAGES - 1), lt);
        CP_COMMIT();
        CP_WAIT(STAGES - 1);
        __syncthreads();

        int s = kt & (STAGES - 1);
        uint32_t aS = aBase + s * STAGE_BYTES;
        uint32_t bS = bBase + s * STAGE_BYTES;
        #pragma unroll
        for (int kk = 0; kk < 2; kk++) {        // two k16 steps per BK=32
            uint32_t a[4][4], b[4][4];
            #pragma unroll
            for (int mi = 0; mi < 4; mi++)
                ldsm4(a[mi], aS + mi * (16 * PITCH * 2) + kk * 32);
            #pragma unroll
            for (int nj2 = 0; nj2 < 4; nj2++)
                ldsm4(b[nj2], bS + nj2 * (16 * PITCH * 2) + kk * 32);
            #pragma unroll
            for (int mi = 0; mi < 4; mi++)
                #pragma unroll
                for (int nj = 0; nj < 8; nj++)
                    mma16816(acc[mi][nj], a[mi],
                             b[nj >> 1][(nj & 1) * 2], b[nj >> 1][(nj & 1) * 2 + 1]);
        }
        __syncthreads();
    }

    // ---- epilogue: + bias, fp32 stores ----
    float* outp = out + (size_t)(m_tile * BM) * N_TOTAL + (size_t)n_tile * BN;
    const float* biasp = bias + (size_t)n_tile * BN;
    #pragma unroll
    for (int mi = 0; mi < 4; mi++) {
        int r0 = m_off + mi * 16 + (lane >> 2);
        #pragma unroll
        for (int nj = 0; nj < 8; nj++) {
            int c0 = n_off + nj * 8 + (lane & 3) * 2;
            float2 bv = *(const float2*)(biasp + c0);
            float2 v0, v1;
            v0.x = acc[mi][nj][0] + bv.x;
            v0.y = acc[mi][nj][1] + bv.y;
            v1.x = acc[mi][nj][2] + bv.x;
            v1.y = acc[mi][nj][3] + bv.y;
            *(float2*)(outp + (size_t)r0 * N_TOTAL + c0) = v0;
            *(float2*)(outp + (size_t)(r0 + 8) * N_TOTAL + c0) = v1;
        }
    }
}

// ---------------------------------------------------------------------------
extern "C" void kernel_launch(void* const* d_in, const int* in_sizes, int n_in,
                              void* d_out, int out_size) {
    const float* x    = (const float*)d_in[0];
    const int*   qw   = (const int*)d_in[1];
    const float* sw   = (const float*)d_in[2];
    const float* bias = (const float*)d_in[3];
    float* out = (float*)d_out;

    prep_x_kernel<<<(M_TOTAL * (K_TOTAL / 4)) / 256, 256>>>(x);
    prep_w_kernel<<<(N_TOTAL * (K_TOTAL / 4)) / 256, 256>>>(qw, sw);

    cudaFuncSetAttribute(qgl_gemm_kernel,
                         cudaFuncAttributeMaxDynamicSharedMemorySize, SMEM_TOTAL);
    qgl_gemm_kernel<<<TILES_M * TILES_N, 256, SMEM_TOTAL>>>(bias, out);
}

// round 3
// speedup vs baseline: 1.2232x; 1.2232x over previous
#include <cuda_runtime.h>
#include <cuda_fp16.h>
#include <cstdint>

// ---------------------------------------------------------------------------
// QGroupLinear: y = x @ (qw*sw)^T + bias   (fp32 in/out)
// mma.sync (HMMA) pipelined GEMM; fp16 dequant scratch (rel_err ~3e-4).
// R3: BK=64, single __syncthreads per k-iter, loads issued before compute,
// register double-buffered fragments.
// ---------------------------------------------------------------------------

#define M_TOTAL 4096
#define N_TOTAL 11008
#define K_TOTAL 4096

#define BM 128
#define BN 256
#define BK 64
#define STAGES 4
#define KT (K_TOTAL / BK)          // 64
#define TILES_M (M_TOTAL / BM)     // 32
#define TILES_N (N_TOTAL / BN)     // 43

#define PITCH 72                    // halfs per smem row (144 B) -> conflict-free ldmatrix
#define A_SM_BYTES (BM * PITCH * 2) // 18432
#define B_SM_BYTES (BN * PITCH * 2) // 36864
#define STAGE_BYTES (A_SM_BYTES + B_SM_BYTES)          // 55296
#define SMEM_TOTAL (STAGES * STAGE_BYTES)              // 221184

__device__ __half d_X16[16777216];   // 32 MB  (4096*4096)
__device__ __half d_W16[45088768];   // 90 MB  (11008*4096)

// ---------------------------------------------------------------------------
__device__ __forceinline__ uint32_t smem_u32(const void* p) {
    uint32_t a;
    asm("{ .reg .u64 t; cvta.to.shared.u64 t, %1; cvt.u32.u64 %0, t; }"
        : "=r"(a) : "l"(p));
    return a;
}

__device__ __forceinline__ void cp_async16(uint32_t dst, const void* src) {
    asm volatile("cp.async.cg.shared.global [%0], [%1], 16;"
                 :: "r"(dst), "l"(__cvta_generic_to_global(src)) : "memory");
}
#define CP_COMMIT() asm volatile("cp.async.commit_group;" ::: "memory")
#define CP_WAIT(n)  asm volatile("cp.async.wait_group %0;" :: "n"(n) : "memory")

__device__ __forceinline__ void ldsm4(uint32_t* r, uint32_t addr) {
    asm volatile("ldmatrix.sync.aligned.m8n8.x4.shared.b16 {%0,%1,%2,%3}, [%4];"
                 : "=r"(r[0]), "=r"(r[1]), "=r"(r[2]), "=r"(r[3]) : "r"(addr));
}

__device__ __forceinline__ void mma16816(float* c, const uint32_t* a,
                                         uint32_t b0, uint32_t b1) {
    asm volatile(
        "mma.sync.aligned.m16n8k16.row.col.f32.f16.f16.f32 "
        "{%0,%1,%2,%3}, {%4,%5,%6,%7}, {%8,%9}, {%0,%1,%2,%3};"
        : "+f"(c[0]), "+f"(c[1]), "+f"(c[2]), "+f"(c[3])
        : "r"(a[0]), "r"(a[1]), "r"(a[2]), "r"(a[3]), "r"(b0), "r"(b1));
}

// ---------------------------------------------------------------------------
// Prep kernels: dequant/convert to plain row-major fp16
// ---------------------------------------------------------------------------
__global__ void __launch_bounds__(256) prep_x_kernel(const float* __restrict__ x) {
    int idx = blockIdx.x * blockDim.x + threadIdx.x;      // 1 thread per 4 elems
    size_t base = (size_t)idx * 4;
    float4 v = *(const float4*)(x + base);
    __half2 h01 = __floats2half2_rn(v.x, v.y);
    __half2 h23 = __floats2half2_rn(v.z, v.w);
    uint2 pk;
    pk.x = *(uint32_t*)&h01;
    pk.y = *(uint32_t*)&h23;
    *(uint2*)(d_X16 + base) = pk;
}

__global__ void __launch_bounds__(256) prep_w_kernel(const int* __restrict__ qw,
                                                     const float* __restrict__ sw) {
    int idx = blockIdx.x * blockDim.x + threadIdx.x;      // 1 thread per 4 elems
    int n = idx >> 10;                                    // K/4 = 1024 per row
    int k0 = (idx & 1023) << 2;
    int4 q = *(const int4*)(qw + (size_t)n * K_TOTAL + k0);
    float s = sw[n * 32 + (k0 >> 7)];
    __half2 h01 = __floats2half2_rn((float)q.x * s, (float)q.y * s);
    __half2 h23 = __floats2half2_rn((float)q.z * s, (float)q.w * s);
    uint2 pk;
    pk.x = *(uint32_t*)&h01;
    pk.y = *(uint32_t*)&h23;
    *(uint2*)(d_W16 + (size_t)n * K_TOTAL + k0) = pk;
}

// ---------------------------------------------------------------------------
// GEMM: 256 threads, 8 warps as 2(m) x 4(n), warp tile 64x64, BK=64.
// ---------------------------------------------------------------------------
__global__ void __launch_bounds__(256, 1) qgl_gemm_kernel(const float* __restrict__ bias,
                                                          float* __restrict__ out) {
    extern __shared__ char smem[];
    uint32_t sb = smem_u32(smem);
    int tid = threadIdx.x;
    int lane = tid & 31;
    int wid = tid >> 5;
    int warp_m = wid & 1;
    int warp_n = wid >> 1;
    int m_off = warp_m * 64;
    int n_off = warp_n * 64;

    // grouped-M tile swizzle for L2 locality (8 m-tiles per group)
    int bid = blockIdx.x;
    int group = bid / (8 * TILES_N);
    int rem = bid - group * (8 * TILES_N);
    int m_tile = group * 8 + (rem & 7);
    int n_tile = rem >> 3;

    const __half* xg = d_X16 + (size_t)(m_tile * BM) * K_TOTAL;
    const __half* wg = d_W16 + (size_t)(n_tile * BN) * K_TOTAL;

    // cp.async 16B chunk coords: 8 chunks per 128B k-row
    // A: 1024 chunks -> 4/thread ; B: 2048 chunks -> 8/thread
    int ca_row = tid >> 3;                 // 0..31
    int ca_col = (tid & 7) * 8;            // halfs

    // ldmatrix per-lane base addresses
    uint32_t aBase = sb + (uint32_t)((m_off + (lane & 15)) * PITCH + ((lane >> 4) << 3)) * 2;
    int rowB = (lane & 7) | ((lane & 16) >> 1);
    uint32_t bBase = sb + A_SM_BYTES
                   + (uint32_t)((n_off + rowB) * PITCH + (((lane >> 3) & 1) << 3)) * 2;

    float acc[4][8][4];
    #pragma unroll
    for (int mi = 0; mi < 4; mi++)
        #pragma unroll
        for (int nj = 0; nj < 8; nj++)
            #pragma unroll
            for (int r = 0; r < 4; r++) acc[mi][nj][r] = 0.0f;

    auto load_stage = [&](int s, int kt) {
        uint32_t as = sb + s * STAGE_BYTES;
        uint32_t bs = as + A_SM_BYTES;
        int k0 = kt * BK;
        #pragma unroll
        for (int i = 0; i < 4; i++) {
            int row = ca_row + i * 32;
            cp_async16(as + (uint32_t)(row * PITCH + ca_col) * 2,
                       xg + (size_t)row * K_TOTAL + k0 + ca_col);
        }
        #pragma unroll
        for (int i = 0; i < 8; i++) {
            int row = ca_row + i * 32;
            cp_async16(bs + (uint32_t)(row * PITCH + ca_col) * 2,
                       wg + (size_t)row * K_TOTAL + k0 + ca_col);
        }
    };

    // prologue: stages 0..2
    #pragma unroll
    for (int s = 0; s < STAGES - 1; s++) {
        load_stage(s, s);
        CP_COMMIT();
    }

    uint32_t fa[2][4][4], fb[2][4][4];

    for (int kt = 0; kt < KT; kt++) {
        CP_WAIT(2);
        __syncthreads();
        // issue next loads FIRST (overlap with this tile's MMAs).
        // writes stage (kt+3)&3 == (kt-1)&3, whose reads finished in iter kt-1
        // (guaranteed by the sync above).
        int lt = kt + STAGES - 1;
        if (lt < KT) load_stage(lt & (STAGES - 1), lt);
        CP_COMMIT();

        int s = kt & (STAGES - 1);
        uint32_t aS = aBase + s * STAGE_BYTES;
        uint32_t bS = bBase + s * STAGE_BYTES;

        // prime kk=0 fragments
        #pragma unroll
        for (int mi = 0; mi < 4; mi++)
            ldsm4(fa[0][mi], aS + mi * (16 * PITCH * 2));
        #pragma unroll
        for (int nj2 = 0; nj2 < 4; nj2++)
            ldsm4(fb[0][nj2], bS + nj2 * (16 * PITCH * 2));

        #pragma unroll
        for (int kk = 0; kk < 4; kk++) {     // four k16 steps per BK=64
            int cur = kk & 1, nxt = cur ^ 1;
            if (kk < 3) {
                #pragma unroll
                for (int mi = 0; mi < 4; mi++)
                    ldsm4(fa[nxt][mi], aS + mi * (16 * PITCH * 2) + (kk + 1) * 32);
                #pragma unroll
                for (int nj2 = 0; nj2 < 4; nj2++)
                    ldsm4(fb[nxt][nj2], bS + nj2 * (16 * PITCH * 2) + (kk + 1) * 32);
            }
            #pragma unroll
            for (int mi = 0; mi < 4; mi++)
                #pragma unroll
                for (int nj = 0; nj < 8; nj++)
                    mma16816(acc[mi][nj], fa[cur][mi],
                             fb[cur][nj >> 1][(nj & 1) * 2],
                             fb[cur][nj >> 1][(nj & 1) * 2 + 1]);
        }
    }

    // ---- epilogue: + bias, fp32 stores ----
    float* outp = out + (size_t)(m_tile * BM) * N_TOTAL + (size_t)n_tile * BN;
    const float* biasp = bias + (size_t)n_tile * BN;
    #pragma unroll
    for (int mi = 0; mi < 4; mi++) {
        int r0 = m_off + mi * 16 + (lane >> 2);
        #pragma unroll
        for (int nj = 0; nj < 8; nj++) {
            int c0 = n_off + nj * 8 + (lane & 3) * 2;
            float2 bv = *(const float2*)(biasp + c0);
            float2 v0, v1;
            v0.x = acc[mi][nj][0] + bv.x;
            v0.y = acc[mi][nj][1] + bv.y;
            v1.x = acc[mi][nj][2] + bv.x;
            v1.y = acc[mi][nj][3] + bv.y;
            *(float2*)(outp + (size_t)r0 * N_TOTAL + c0) = v0;
            *(float2*)(outp + (size_t)(r0 + 8) * N_TOTAL + c0) = v1;
        }
    }
}

// ---------------------------------------------------------------------------
extern "C" void kernel_launch(void* const* d_in, const int* in_sizes, int n_in,
                              void* d_out, int out_size) {
    const float* x    = (const float*)d_in[0];
    const int*   qw   = (const int*)d_in[1];
    const float* sw   = (const float*)d_in[2];
    const float* bias = (const float*)d_in[3];
    float* out = (float*)d_out;

    prep_x_kernel<<<(M_TOTAL * (K_TOTAL / 4)) / 256, 256>>>(x);
    prep_w_kernel<<<(N_TOTAL * (K_TOTAL / 4)) / 256, 256>>>(qw, sw);

    cudaFuncSetAttribute(qgl_gemm_kernel,
                         cudaFuncAttributeMaxDynamicSharedMemorySize, SMEM_TOTAL);
    qgl_gemm_kernel<<<TILES_M * TILES_N, 256, SMEM_TOTAL>>>(bias, out);
}

// round 4
// speedup vs baseline: 1.5654x; 1.2798x over previous
#include <cuda_runtime.h>
#include <cuda_fp16.h>
#include <cstdint>

// ---------------------------------------------------------------------------
// QGroupLinear: y = x @ (qw*sw)^T + bias   (fp32 in/out)
// mma.sync (HMMA) GEMM, fp16 dequant scratch (rel_err ~3e-4).
// R4: fully software-pipelined mainloop — fragments always prefetched one
// k16-step ahead (across stage boundaries), wait-two-stages-ahead cp.async
// protocol so no ldsm/wait/barrier sits on the MMA critical path.
// ---------------------------------------------------------------------------

#define M_TOTAL 4096
#define N_TOTAL 11008
#define K_TOTAL 4096

#define BM 128
#define BN 256
#define BK 64
#define STAGES 4
#define KT (K_TOTAL / BK)          // 64
#define TILES_M (M_TOTAL / BM)     // 32
#define TILES_N (N_TOTAL / BN)     // 43

#define PITCH 72                    // halfs per smem row (144 B) -> conflict-free ldmatrix
#define A_SM_BYTES (BM * PITCH * 2) // 18432
#define B_SM_BYTES (BN * PITCH * 2) // 36864
#define STAGE_BYTES (A_SM_BYTES + B_SM_BYTES)          // 55296
#define SMEM_TOTAL (STAGES * STAGE_BYTES)              // 221184

__device__ __half d_X16[16777216];   // 32 MB  (4096*4096)
__device__ __half d_W16[45088768];   // 90 MB  (11008*4096)

// ---------------------------------------------------------------------------
__device__ __forceinline__ uint32_t smem_u32(const void* p) {
    uint32_t a;
    asm("{ .reg .u64 t; cvta.to.shared.u64 t, %1; cvt.u32.u64 %0, t; }"
        : "=r"(a) : "l"(p));
    return a;
}

__device__ __forceinline__ void cp_async16(uint32_t dst, const void* src) {
    asm volatile("cp.async.cg.shared.global [%0], [%1], 16;"
                 :: "r"(dst), "l"(__cvta_generic_to_global(src)) : "memory");
}
#define CP_COMMIT() asm volatile("cp.async.commit_group;" ::: "memory")
#define CP_WAIT(n)  asm volatile("cp.async.wait_group %0;" :: "n"(n) : "memory")

__device__ __forceinline__ void ldsm4(uint32_t* r, uint32_t addr) {
    asm volatile("ldmatrix.sync.aligned.m8n8.x4.shared.b16 {%0,%1,%2,%3}, [%4];"
                 : "=r"(r[0]), "=r"(r[1]), "=r"(r[2]), "=r"(r[3]) : "r"(addr));
}

__device__ __forceinline__ void mma16816(float* c, const uint32_t* a,
                                         uint32_t b0, uint32_t b1) {
    asm volatile(
        "mma.sync.aligned.m16n8k16.row.col.f32.f16.f16.f32 "
        "{%0,%1,%2,%3}, {%4,%5,%6,%7}, {%8,%9}, {%0,%1,%2,%3};"
        : "+f"(c[0]), "+f"(c[1]), "+f"(c[2]), "+f"(c[3])
        : "r"(a[0]), "r"(a[1]), "r"(a[2]), "r"(a[3]), "r"(b0), "r"(b1));
}

// ---------------------------------------------------------------------------
// Prep kernels: dequant/convert to plain row-major fp16
// ---------------------------------------------------------------------------
__global__ void __launch_bounds__(256) prep_x_kernel(const float* __restrict__ x) {
    int idx = blockIdx.x * blockDim.x + threadIdx.x;      // 1 thread per 4 elems
    size_t base = (size_t)idx * 4;
    float4 v = *(const float4*)(x + base);
    __half2 h01 = __floats2half2_rn(v.x, v.y);
    __half2 h23 = __floats2half2_rn(v.z, v.w);
    uint2 pk;
    pk.x = *(uint32_t*)&h01;
    pk.y = *(uint32_t*)&h23;
    *(uint2*)(d_X16 + base) = pk;
}

__global__ void __launch_bounds__(256) prep_w_kernel(const int* __restrict__ qw,
                                                     const float* __restrict__ sw) {
    int idx = blockIdx.x * blockDim.x + threadIdx.x;      // 1 thread per 4 elems
    int n = idx >> 10;                                    // K/4 = 1024 per row
    int k0 = (idx & 1023) << 2;
    int4 q = *(const int4*)(qw + (size_t)n * K_TOTAL + k0);
    float s = sw[n * 32 + (k0 >> 7)];
    __half2 h01 = __floats2half2_rn((float)q.x * s, (float)q.y * s);
    __half2 h23 = __floats2half2_rn((float)q.z * s, (float)q.w * s);
    uint2 pk;
    pk.x = *(uint32_t*)&h01;
    pk.y = *(uint32_t*)&h23;
    *(uint2*)(d_W16 + (size_t)n * K_TOTAL + k0) = pk;
}

// ---------------------------------------------------------------------------
// GEMM: 256 threads, 8 warps as 2(m) x 4(n), warp tile 64x64, BK=64.
// Pipeline invariant at top of iteration kt:
//   - stages kt and kt+1 are COMPLETE and barrier-published to all warps
//   - stage kt+2 is in flight
//   - fragments for (kt, kk=0) are already in registers
// ---------------------------------------------------------------------------
__global__ void __launch_bounds__(256, 1) qgl_gemm_kernel(const float* __restrict__ bias,
                                                          float* __restrict__ out) {
    extern __shared__ char smem[];
    uint32_t sb = smem_u32(smem);
    int tid = threadIdx.x;
    int lane = tid & 31;
    int wid = tid >> 5;
    int warp_m = wid & 1;
    int warp_n = wid >> 1;
    int m_off = warp_m * 64;
    int n_off = warp_n * 64;

    // grouped-M tile swizzle for L2 locality (8 m-tiles per group)
    int bid = blockIdx.x;
    int group = bid / (8 * TILES_N);
    int rem = bid - group * (8 * TILES_N);
    int m_tile = group * 8 + (rem & 7);
    int n_tile = rem >> 3;

    const __half* xg = d_X16 + (size_t)(m_tile * BM) * K_TOTAL;
    const __half* wg = d_W16 + (size_t)(n_tile * BN) * K_TOTAL;

    // cp.async 16B chunk coords: 8 chunks per 128B k-row
    int ca_row = tid >> 3;                 // 0..31
    int ca_col = (tid & 7) * 8;            // halfs

    // ldmatrix per-lane base addresses
    uint32_t aBase = sb + (uint32_t)((m_off + (lane & 15)) * PITCH + ((lane >> 4) << 3)) * 2;
    int rowB = (lane & 7) | ((lane & 16) >> 1);
    uint32_t bBase = sb + A_SM_BYTES
                   + (uint32_t)((n_off + rowB) * PITCH + (((lane >> 3) & 1) << 3)) * 2;

    float acc[4][8][4];
    #pragma unroll
    for (int mi = 0; mi < 4; mi++)
        #pragma unroll
        for (int nj = 0; nj < 8; nj++)
            #pragma unroll
            for (int r = 0; r < 4; r++) acc[mi][nj][r] = 0.0f;

    auto load_stage = [&](int s, int kt) {
        uint32_t as = sb + s * STAGE_BYTES;
        uint32_t bs = as + A_SM_BYTES;
        int k0 = kt * BK;
        #pragma unroll
        for (int i = 0; i < 4; i++) {
            int row = ca_row + i * 32;
            cp_async16(as + (uint32_t)(row * PITCH + ca_col) * 2,
                       xg + (size_t)row * K_TOTAL + k0 + ca_col);
        }
        #pragma unroll
        for (int i = 0; i < 8; i++) {
            int row = ca_row + i * 32;
            cp_async16(bs + (uint32_t)(row * PITCH + ca_col) * 2,
                       wg + (size_t)row * K_TOTAL + k0 + ca_col);
        }
    };

    uint32_t fa[2][4][4], fb[2][4][4];

    auto prefetch = [&](int buf, int s, int kk) {
        uint32_t aS = aBase + s * STAGE_BYTES + kk * 32;
        uint32_t bS = bBase + s * STAGE_BYTES + kk * 32;
        #pragma unroll
        for (int mi = 0; mi < 4; mi++)
            ldsm4(fa[buf][mi], aS + mi * (16 * PITCH * 2));
        #pragma unroll
        for (int nj2 = 0; nj2 < 4; nj2++)
            ldsm4(fb[buf][nj2], bS + nj2 * (16 * PITCH * 2));
    };

    // ---- prologue: stages 0,1,2 in flight; publish 0 and 1; prime (0,0) ----
    #pragma unroll
    for (int s = 0; s < STAGES - 1; s++) {
        load_stage(s, s);
        CP_COMMIT();
    }
    CP_WAIT(1);            // stages 0 and 1 complete (own groups)
    __syncthreads();       // publish to all warps
    prefetch(0, 0, 0);

    for (int kt = 0; kt < KT; kt++) {
        // issue load for stage kt+3 (overwrites stage (kt-1)&3; all warps
        // finished reading it before the barrier at the end of iter kt-1)
        if (kt + STAGES - 1 < KT) load_stage((kt + STAGES - 1) & (STAGES - 1), kt + STAGES - 1);
        CP_COMMIT();

        int s = kt & (STAGES - 1);
        #pragma unroll
        for (int kk = 0; kk < 4; kk++) {
            int cur = kk & 1, nxt = cur ^ 1;
            if (kk < 3)
                prefetch(nxt, s, kk + 1);
            else if (kt + 1 < KT)
                prefetch(nxt, (kt + 1) & (STAGES - 1), 0);   // stage kt+1 already published
            #pragma unroll
            for (int mi = 0; mi < 4; mi++)
                #pragma unroll
                for (int nj = 0; nj < 8; nj++)
                    mma16816(acc[mi][nj], fa[cur][mi],
                             fb[cur][nj >> 1][(nj & 1) * 2],
                             fb[cur][nj >> 1][(nj & 1) * 2 + 1]);
        }

        // complete group kt+2 (leaving kt+3 in flight) and publish it, so
        // iteration kt+1 may read stage kt+2 at its kk=3 cross-stage prefetch.
        CP_WAIT(1);
        __syncthreads();
    }

    // ---- epilogue: + bias, fp32 stores ----
    float* outp = out + (size_t)(m_tile * BM) * N_TOTAL + (size_t)n_tile * BN;
    const float* biasp = bias + (size_t)n_tile * BN;
    #pragma unroll
    for (int mi = 0; mi < 4; mi++) {
        int r0 = m_off + mi * 16 + (lane >> 2);
        #pragma unroll
        for (int nj = 0; nj < 8; nj++) {
            int c0 = n_off + nj * 8 + (lane & 3) * 2;
            float2 bv = *(const float2*)(biasp + c0);
            float2 v0, v1;
            v0.x = acc[mi][nj][0] + bv.x;
            v0.y = acc[mi][nj][1] + bv.y;
            v1.x = acc[mi][nj][2] + bv.x;
            v1.y = acc[mi][nj][3] + bv.y;
            *(float2*)(outp + (size_t)r0 * N_TOTAL + c0) = v0;
            *(float2*)(outp + (size_t)(r0 + 8) * N_TOTAL + c0) = v1;
        }
    }
}

// ---------------------------------------------------------------------------
extern "C" void kernel_launch(void* const* d_in, const int* in_sizes, int n_in,
                              void* d_out, int out_size) {
    const float* x    = (const float*)d_in[0];
    const int*   qw   = (const int*)d_in[1];
    const float* sw   = (const float*)d_in[2];
    const float* bias = (const float*)d_in[3];
    float* out = (float*)d_out;

    prep_x_kernel<<<(M_TOTAL * (K_TOTAL / 4)) / 256, 256>>>(x);
    prep_w_kernel<<<(N_TOTAL * (K_TOTAL / 4)) / 256, 256>>>(qw, sw);

    cudaFuncSetAttribute(qgl_gemm_kernel,
                         cudaFuncAttributeMaxDynamicSharedMemorySize, SMEM_TOTAL);
    qgl_gemm_kernel<<<TILES_M * TILES_N, 256, SMEM_TOTAL>>>(bias, out);
}

// round 5
// speedup vs baseline: 1.7387x; 1.1107x over previous
#include <cuda_runtime.h>
#include <cuda_fp16.h>
#include <cstdint>

// ---------------------------------------------------------------------------
// QGroupLinear: y = x @ (qw*sw)^T + bias   (fp32 in/out)
// mma.sync (HMMA) GEMM, fp16 dequant scratch (rel_err ~3e-4).
// R5: fused prep kernel, column-major tile order (single-pass DRAM streaming
// of W/X, L2-resident working set), cp.async issue smoothed across kk steps.
// ---------------------------------------------------------------------------

#define M_TOTAL 4096
#define N_TOTAL 11008
#define K_TOTAL 4096

#define BM 128
#define BN 256
#define BK 64
#define STAGES 4
#define KT (K_TOTAL / BK)          // 64
#define TILES_M (M_TOTAL / BM)     // 32
#define TILES_N (N_TOTAL / BN)     // 43

#define PITCH 72                    // halfs per smem row (144 B) -> conflict-free ldmatrix
#define A_SM_BYTES (BM * PITCH * 2) // 18432
#define B_SM_BYTES (BN * PITCH * 2) // 36864
#define STAGE_BYTES (A_SM_BYTES + B_SM_BYTES)          // 55296
#define SMEM_TOTAL (STAGES * STAGE_BYTES)              // 221184

__device__ __half d_X16[16777216];   // 32 MB  (4096*4096)
__device__ __half d_W16[45088768];   // 90 MB  (11008*4096)

// ---------------------------------------------------------------------------
__device__ __forceinline__ uint32_t smem_u32(const void* p) {
    uint32_t a;
    asm("{ .reg .u64 t; cvta.to.shared.u64 t, %1; cvt.u32.u64 %0, t; }"
        : "=r"(a) : "l"(p));
    return a;
}

__device__ __forceinline__ void cp_async16(uint32_t dst, const void* src) {
    asm volatile("cp.async.cg.shared.global [%0], [%1], 16;"
                 :: "r"(dst), "l"(__cvta_generic_to_global(src)) : "memory");
}
#define CP_COMMIT() asm volatile("cp.async.commit_group;" ::: "memory")
#define CP_WAIT(n)  asm volatile("cp.async.wait_group %0;" :: "n"(n) : "memory")

__device__ __forceinline__ void ldsm4(uint32_t* r, uint32_t addr) {
    asm volatile("ldmatrix.sync.aligned.m8n8.x4.shared.b16 {%0,%1,%2,%3}, [%4];"
                 : "=r"(r[0]), "=r"(r[1]), "=r"(r[2]), "=r"(r[3]) : "r"(addr));
}

__device__ __forceinline__ void mma16816(float* c, const uint32_t* a,
                                         uint32_t b0, uint32_t b1) {
    asm volatile(
        "mma.sync.aligned.m16n8k16.row.col.f32.f16.f16.f32 "
        "{%0,%1,%2,%3}, {%4,%5,%6,%7}, {%8,%9}, {%0,%1,%2,%3};"
        : "+f"(c[0]), "+f"(c[1]), "+f"(c[2]), "+f"(c[3])
        : "r"(a[0]), "r"(a[1]), "r"(a[2]), "r"(a[3]), "r"(b0), "r"(b1));
}

// ---------------------------------------------------------------------------
// Fused prep kernel: first X_BLOCKS blocks convert x, rest dequantize w.
// ---------------------------------------------------------------------------
#define X_BLOCKS ((M_TOTAL * (K_TOTAL / 4)) / 256)            // 16384
#define W_BLOCKS ((N_TOTAL * (K_TOTAL / 4)) / 256)            // 44032

__global__ void __launch_bounds__(256) prep_kernel(const float* __restrict__ x,
                                                   const int* __restrict__ qw,
                                                   const float* __restrict__ sw) {
    int b = blockIdx.x;
    if (b < X_BLOCKS) {
        int idx = b * 256 + threadIdx.x;
        size_t base = (size_t)idx * 4;
        float4 v = *(const float4*)(x + base);
        __half2 h01 = __floats2half2_rn(v.x, v.y);
        __half2 h23 = __floats2half2_rn(v.z, v.w);
        uint2 pk;
        pk.x = *(uint32_t*)&h01;
        pk.y = *(uint32_t*)&h23;
        *(uint2*)(d_X16 + base) = pk;
    } else {
        int idx = (b - X_BLOCKS) * 256 + threadIdx.x;
        int n = idx >> 10;                                    // K/4 = 1024 per row
        int k0 = (idx & 1023) << 2;
        int4 q = *(const int4*)(qw + (size_t)n * K_TOTAL + k0);
        float s = sw[n * 32 + (k0 >> 7)];
        __half2 h01 = __floats2half2_rn((float)q.x * s, (float)q.y * s);
        __half2 h23 = __floats2half2_rn((float)q.z * s, (float)q.w * s);
        uint2 pk;
        pk.x = *(uint32_t*)&h01;
        pk.y = *(uint32_t*)&h23;
        *(uint2*)(d_W16 + (size_t)n * K_TOTAL + k0) = pk;
    }
}

// ---------------------------------------------------------------------------
// GEMM: 256 threads, 8 warps as 2(m) x 4(n), warp tile 64x64, BK=64.
// Pipeline invariant at top of iteration kt:
//   - stages kt and kt+1 are COMPLETE and barrier-published to all warps
//   - stage kt+2 is in flight
//   - fragments for (kt, kk=0) are already in registers
// ---------------------------------------------------------------------------
__global__ void __launch_bounds__(256, 1) qgl_gemm_kernel(const float* __restrict__ bias,
                                                          float* __restrict__ out) {
    extern __shared__ char smem[];
    uint32_t sb = smem_u32(smem);
    int tid = threadIdx.x;
    int lane = tid & 31;
    int wid = tid >> 5;
    int warp_m = wid & 1;
    int warp_n = wid >> 1;
    int m_off = warp_m * 64;
    int n_off = warp_n * 64;

    // column-major tile order: a wave of 148 CTAs spans all 32 m-tiles and
    // ~5 n-tiles -> X fully L2-resident, W streamed from DRAM exactly once.
    int bid = blockIdx.x;
    int m_tile = bid & (TILES_M - 1);
    int n_tile = bid >> 5;

    const __half* xg = d_X16 + (size_t)(m_tile * BM) * K_TOTAL;
    const __half* wg = d_W16 + (size_t)(n_tile * BN) * K_TOTAL;

    // cp.async 16B chunk coords: 8 chunks per 128B k-row
    int ca_row = tid >> 3;                 // 0..31
    int ca_col = (tid & 7) * 8;            // halfs

    // ldmatrix per-lane base addresses
    uint32_t aBase = sb + (uint32_t)((m_off + (lane & 15)) * PITCH + ((lane >> 4) << 3)) * 2;
    int rowB = (lane & 7) | ((lane & 16) >> 1);
    uint32_t bBase = sb + A_SM_BYTES
                   + (uint32_t)((n_off + rowB) * PITCH + (((lane >> 3) & 1) << 3)) * 2;

    float acc[4][8][4];
    #pragma unroll
    for (int mi = 0; mi < 4; mi++)
        #pragma unroll
        for (int nj = 0; nj < 8; nj++)
            #pragma unroll
            for (int r = 0; r < 4; r++) acc[mi][nj][r] = 0.0f;

    // full-stage loader (prologue only)
    auto load_stage = [&](int s, int kt) {
        uint32_t as = sb + s * STAGE_BYTES;
        uint32_t bs = as + A_SM_BYTES;
        int k0 = kt * BK;
        #pragma unroll
        for (int i = 0; i < 4; i++) {
            int row = ca_row + i * 32;
            cp_async16(as + (uint32_t)(row * PITCH + ca_col) * 2,
                       xg + (size_t)row * K_TOTAL + k0 + ca_col);
        }
        #pragma unroll
        for (int i = 0; i < 8; i++) {
            int row = ca_row + i * 32;
            cp_async16(bs + (uint32_t)(row * PITCH + ca_col) * 2,
                       wg + (size_t)row * K_TOTAL + k0 + ca_col);
        }
    };

    // partial loader: slice sl in [0,4) issues 3 of the 12 chunks, so the
    // producer traffic is spread across the kk sub-steps (burst smoothing).
    auto load_slice = [&](int s, int kt, int sl) {
        uint32_t as = sb + s * STAGE_BYTES;
        uint32_t bs = as + A_SM_BYTES;
        int k0 = kt * BK;
        {   // A chunk sl
            int row = ca_row + sl * 32;
            cp_async16(as + (uint32_t)(row * PITCH + ca_col) * 2,
                       xg + (size_t)row * K_TOTAL + k0 + ca_col);
        }
        #pragma unroll
        for (int i = 0; i < 2; i++) {   // B chunks 2*sl, 2*sl+1
            int row = ca_row + (sl * 2 + i) * 32;
            cp_async16(bs + (uint32_t)(row * PITCH + ca_col) * 2,
                       wg + (size_t)row * K_TOTAL + k0 + ca_col);
        }
    };

    uint32_t fa[2][4][4], fb[2][4][4];

    auto prefetch = [&](int buf, int s, int kk) {
        uint32_t aS = aBase + s * STAGE_BYTES + kk * 32;
        uint32_t bS = bBase + s * STAGE_BYTES + kk * 32;
        #pragma unroll
        for (int mi = 0; mi < 4; mi++)
            ldsm4(fa[buf][mi], aS + mi * (16 * PITCH * 2));
        #pragma unroll
        for (int nj2 = 0; nj2 < 4; nj2++)
            ldsm4(fb[buf][nj2], bS + nj2 * (16 * PITCH * 2));
    };

    // ---- prologue: stages 0,1,2 in flight; publish 0 and 1; prime (0,0) ----
    #pragma unroll
    for (int s = 0; s < STAGES - 1; s++) {
        load_stage(s, s);
        CP_COMMIT();
    }
    CP_WAIT(1);            // stages 0 and 1 complete (own groups)
    __syncthreads();       // publish to all warps
    prefetch(0, 0, 0);

    for (int kt = 0; kt < KT; kt++) {
        int s = kt & (STAGES - 1);
        int lt = kt + STAGES - 1;                 // stage to load (overwrites (kt-1)&3)
        int ls = lt & (STAGES - 1);
        bool do_load = (lt < KT);

        #pragma unroll
        for (int kk = 0; kk < 4; kk++) {
            int cur = kk & 1, nxt = cur ^ 1;
            // smooth producer: 3 cp.async per kk
            if (do_load) load_slice(ls, lt, kk);
            if (kk == 3) CP_COMMIT();
            if (kk < 3)
                prefetch(nxt, s, kk + 1);
            else if (kt + 1 < KT)
                prefetch(nxt, (kt + 1) & (STAGES - 1), 0);   // stage kt+1 already published
            #pragma unroll
            for (int mi = 0; mi < 4; mi++)
                #pragma unroll
                for (int nj = 0; nj < 8; nj++)
                    mma16816(acc[mi][nj], fa[cur][mi],
                             fb[cur][nj >> 1][(nj & 1) * 2],
                             fb[cur][nj >> 1][(nj & 1) * 2 + 1]);
        }

        // complete group kt+2 (leaving kt+3 in flight) and publish it, so
        // iteration kt+1 may read stage kt+2 at its kk=3 cross-stage prefetch.
        CP_WAIT(1);
        __syncthreads();
    }

    // ---- epilogue: + bias, fp32 stores ----
    float* outp = out + (size_t)(m_tile * BM) * N_TOTAL + (size_t)n_tile * BN;
    const float* biasp = bias + (size_t)n_tile * BN;
    #pragma unroll
    for (int mi = 0; mi < 4; mi++) {
        int r0 = m_off + mi * 16 + (lane >> 2);
        #pragma unroll
        for (int nj = 0; nj < 8; nj++) {
            int c0 = n_off + nj * 8 + (lane & 3) * 2;
            float2 bv = *(const float2*)(biasp + c0);
            float2 v0, v1;
            v0.x = acc[mi][nj][0] + bv.x;
            v0.y = acc[mi][nj][1] + bv.y;
            v1.x = acc[mi][nj][2] + bv.x;
            v1.y = acc[mi][nj][3] + bv.y;
            *(float2*)(outp + (size_t)r0 * N_TOTAL + c0) = v0;
            *(float2*)(outp + (size_t)(r0 + 8) * N_TOTAL + c0) = v1;
        }
    }
}

// ---------------------------------------------------------------------------
extern "C" void kernel_launch(void* const* d_in, const int* in_sizes, int n_in,
                              void* d_out, int out_size) {
    const float* x    = (const float*)d_in[0];
    const int*   qw   = (const int*)d_in[1];
    const float* sw   = (const float*)d_in[2];
    const float* bias = (const float*)d_in[3];
    float* out = (float*)d_out;

    prep_kernel<<<X_BLOCKS + W_BLOCKS, 256>>>(x, qw, sw);

    cudaFuncSetAttribute(qgl_gemm_kernel,
                         cudaFuncAttributeMaxDynamicSharedMemorySize, SMEM_TOTAL);
    qgl_gemm_kernel<<<TILES_M * TILES_N, 256, SMEM_TOTAL>>>(bias, out);
}

// round 6
// speedup vs baseline: 1.7555x; 1.0096x over previous
#include <cuda_runtime.h>
#include <cuda_fp16.h>
#include <cstdint>

// ---------------------------------------------------------------------------
// QGroupLinear: y = x @ (qw*sw)^T + bias   (fp32 in/out)
// mma.sync (HMMA) GEMM, fp16 dequant scratch (rel_err ~3e-4).
// R6: prep pre-tiles + pre-SW128-swizzles into contiguous blocks; GEMM uses
// single-thread cp.async.bulk + mbarrier full/empty ring (4 stages) -> NO
// __syncthreads / cp.async.wait_group in the mainloop.
// ---------------------------------------------------------------------------

#define M_TOTAL 4096
#define N_TOTAL 11008
#define K_TOTAL 4096

#define BM 128
#define BN 256
#define BK 64                       // halfs per k-chunk (128 B rows)
#define STAGES 4
#define KT (K_TOTAL / BK)           // 64
#define TILES_M (M_TOTAL / BM)      // 32
#define TILES_N (N_TOTAL / BN)      // 43

#define A_BLK_BYTES (BM * 128)      // 16384
#define B_BLK_BYTES (BN * 128)      // 32768
#define STAGE_BYTES (A_BLK_BYTES + B_BLK_BYTES)   // 49152

// SMEM: [0..31] full mbarriers, [32..63] empty mbarriers, data at 1024
#define SM_FULL(s)  ((s) * 8)
#define SM_EMPTY(s) (32 + (s) * 8)
#define SM_DATA     1024
#define SMEM_TOTAL  (SM_DATA + STAGES * STAGE_BYTES)   // 197632

// tiled + swizzled fp16 scratch (uint4 for 16B-aligned access)
__device__ uint4 d_X16T[2097152];   // 32 MB : block (m_tile*64+kc) = 16 KB
__device__ uint4 d_W16T[5636096];   // 90 MB : block (n_tile*64+kc) = 32 KB

// ---------------------------------------------------------------------------
__device__ __forceinline__ uint32_t smem_u32(const void* p) {
    uint32_t a;
    asm("{ .reg .u64 t; cvta.to.shared.u64 t, %1; cvt.u32.u64 %0, t; }"
        : "=r"(a) : "l"(p));
    return a;
}

#define MBARRIER_INIT(addr, cnt) \
    asm volatile("mbarrier.init.shared.b64 [%0], %1;" :: "r"((uint32_t)(addr)), "r"((uint32_t)(cnt)) : "memory")
#define MBARRIER_EXPECT_TX(addr, bytes) \
    asm volatile("mbarrier.arrive.expect_tx.shared.b64 _, [%0], %1;" :: "r"((uint32_t)(addr)), "r"((uint32_t)(bytes)) : "memory")
#define MBARRIER_ARRIVE(addr) \
    asm volatile("mbarrier.arrive.shared.b64 _, [%0];" :: "r"((uint32_t)(addr)) : "memory")
#define FENCE_PROXY_ASYNC() asm volatile("fence.proxy.async.shared::cta;" ::: "memory")

#define MBARRIER_WAIT_PARITY(mbar_smem_addr, phase_parity) do { \
    uint32_t _mbar = (uint32_t)(mbar_smem_addr); \
    uint32_t _parity = (uint32_t)(phase_parity); \
    uint32_t _done; \
    asm volatile( \
        "{\n\t.reg .pred p;\n\t" \
        "mbarrier.try_wait.parity.acquire.cta.shared::cta.b64 p, [%1], %2;\n\t" \
        "selp.b32 %0, 1, 0, p;\n\t}" \
        : "=r"(_done) : "r"(_mbar), "r"(_parity) : "memory"); \
    if (!_done) { \
        asm volatile( \
            "{\n\t.reg .pred P1;\n\t" \
            "WAIT_LOOP_%=:\n\t" \
            "mbarrier.try_wait.parity.acquire.cta.shared::cta.b64 P1, [%0], %1, 0x989680;\n\t" \
            "@P1 bra.uni WAIT_DONE_%=;\n\t" \
            "bra.uni WAIT_LOOP_%=;\n\t" \
            "WAIT_DONE_%=:\n\t}" \
            :: "r"(_mbar), "r"(_parity) : "memory"); \
    } \
} while (0)

#define BULK_G2S(dst, src, bytes, mbar) \
    asm volatile("cp.async.bulk.shared::cta.global.mbarrier::complete_tx::bytes [%0], [%1], %2, [%3];" \
        :: "r"((uint32_t)(dst)), "l"((unsigned long long)(src)), "r"((uint32_t)(bytes)), "r"((uint32_t)(mbar)) : "memory")

__device__ __forceinline__ void ldsm4(uint32_t* r, uint32_t addr) {
    asm volatile("ldmatrix.sync.aligned.m8n8.x4.shared.b16 {%0,%1,%2,%3}, [%4];"
                 : "=r"(r[0]), "=r"(r[1]), "=r"(r[2]), "=r"(r[3]) : "r"(addr));
}

__device__ __forceinline__ void mma16816(float* c, const uint32_t* a,
                                         uint32_t b0, uint32_t b1) {
    asm volatile(
        "mma.sync.aligned.m16n8k16.row.col.f32.f16.f16.f32 "
        "{%0,%1,%2,%3}, {%4,%5,%6,%7}, {%8,%9}, {%0,%1,%2,%3};"
        : "+f"(c[0]), "+f"(c[1]), "+f"(c[2]), "+f"(c[3])
        : "r"(a[0]), "r"(a[1]), "r"(a[2]), "r"(a[3]), "r"(b0), "r"(b1));
}

// ---------------------------------------------------------------------------
// Fused prep: tiled + SW128-swizzled fp16 blocks. 8 halfs (16 B) per thread,
// two 16B loads in flight (MLP=2).
// ---------------------------------------------------------------------------
#define XB ((M_TOTAL * K_TOTAL / 8) / 256)    // 8192 blocks
#define WB ((N_TOTAL * K_TOTAL / 8) / 256)    // 22016 blocks

__global__ void __launch_bounds__(256) prep_kernel(const float* __restrict__ x,
                                                   const int* __restrict__ qw,
                                                   const float* __restrict__ sw) {
    int b = blockIdx.x;
    if (b < XB) {
        int idx = b * 256 + threadIdx.x;
        int m = idx >> 9;                     // 512 8-half chunks per row
        int k0 = (idx & 511) << 3;
        const float* src = x + (size_t)m * K_TOTAL + k0;
        float4 v0 = *(const float4*)src;
        float4 v1 = *(const float4*)(src + 4);
        __half2 h0 = __floats2half2_rn(v0.x, v0.y);
        __half2 h1 = __floats2half2_rn(v0.z, v0.w);
        __half2 h2 = __floats2half2_rn(v1.x, v1.y);
        __half2 h3 = __floats2half2_rn(v1.z, v1.w);
        uint4 pk;
        pk.x = *(uint32_t*)&h0; pk.y = *(uint32_t*)&h1;
        pk.z = *(uint32_t*)&h2; pk.w = *(uint32_t*)&h3;
        int blk = (m >> 7) * KT + (k0 >> 6);
        int row = m & 127, ch = k0 & 63;
        uint32_t off = (uint32_t)row * 128 + (((uint32_t)ch * 2) ^ (((uint32_t)(row & 7)) << 4));
        *(uint4*)((char*)d_X16T + (((size_t)blk) << 14) + off) = pk;
    } else {
        int idx = (b - XB) * 256 + threadIdx.x;
        int n = idx >> 9;
        int k0 = (idx & 511) << 3;
        const int* src = qw + (size_t)n * K_TOTAL + k0;
        int4 q0 = *(const int4*)src;
        int4 q1 = *(const int4*)(src + 4);
        float s = sw[n * 32 + (k0 >> 7)];
        __half2 h0 = __floats2half2_rn((float)q0.x * s, (float)q0.y * s);
        __half2 h1 = __floats2half2_rn((float)q0.z * s, (float)q0.w * s);
        __half2 h2 = __floats2half2_rn((float)q1.x * s, (float)q1.y * s);
        __half2 h3 = __floats2half2_rn((float)q1.z * s, (float)q1.w * s);
        uint4 pk;
        pk.x = *(uint32_t*)&h0; pk.y = *(uint32_t*)&h1;
        pk.z = *(uint32_t*)&h2; pk.w = *(uint32_t*)&h3;
        int blk = (n >> 8) * KT + (k0 >> 6);
        int row = n & 255, ch = k0 & 63;
        uint32_t off = (uint32_t)row * 128 + (((uint32_t)ch * 2) ^ (((uint32_t)(row & 7)) << 4));
        *(uint4*)((char*)d_W16T + (((size_t)blk) << 15) + off) = pk;
    }
}

// ---------------------------------------------------------------------------
// GEMM: 256 threads, 8 warps as 2(m) x 4(n), warp tile 64x64, BK=64.
// mbarrier ring: full[s] (tx-based, producer tid0), empty[s] (256 arrives).
// Invariant at top of iteration kt: stages kt and kt+1 full-waited;
// stage (kt+3)&3 is being filled; fragments (kt, kk=0) in registers.
// ---------------------------------------------------------------------------
__global__ void __launch_bounds__(256, 1) qgl_gemm_kernel(const float* __restrict__ bias,
                                                          float* __restrict__ out) {
    extern __shared__ char smem[];
    uint32_t sb = smem_u32(smem);
    int tid = threadIdx.x;
    int lane = tid & 31;
    int wid = tid >> 5;
    int warp_m = wid & 1;
    int warp_n = wid >> 1;
    int m_off = warp_m * 64;
    int n_off = warp_n * 64;

    // column-major tile order: one wave spans all 32 m-tiles, ~5 n-tiles
    int bid = blockIdx.x;
    int m_tile = bid & (TILES_M - 1);
    int n_tile = bid >> 5;

    const char* aG = (const char*)d_X16T + (((size_t)m_tile * KT) << 14);
    const char* bG = (const char*)d_W16T + (((size_t)n_tile * KT) << 15);

    if (tid == 0) {
        #pragma unroll
        for (int s = 0; s < STAGES; s++) {
            MBARRIER_INIT(sb + SM_FULL(s), 1);
            MBARRIER_INIT(sb + SM_EMPTY(s), 256);
        }
        FENCE_PROXY_ASYNC();
    }
    __syncthreads();

    // ldmatrix lane addressing with SW128 swizzle
    int rowA = m_off + (lane & 15);
    uint32_t xorA = (uint32_t)(rowA & 7) << 4;
    uint32_t cbA = ((uint32_t)(lane >> 4)) << 4;          // 0 or 16 bytes
    uint32_t aRow = sb + SM_DATA + (uint32_t)rowA * 128;  // stage 0 A base + row

    int rowB = n_off + ((lane & 7) | ((lane & 16) >> 1));
    uint32_t xorB = (uint32_t)(rowB & 7) << 4;
    uint32_t cbB = ((uint32_t)((lane >> 3) & 1)) << 4;
    uint32_t bRow = sb + SM_DATA + A_BLK_BYTES + (uint32_t)rowB * 128;

    float acc[4][8][4];
    #pragma unroll
    for (int mi = 0; mi < 4; mi++)
        #pragma unroll
        for (int nj = 0; nj < 8; nj++)
            #pragma unroll
            for (int r = 0; r < 4; r++) acc[mi][nj][r] = 0.0f;

    uint32_t fa[2][4][4], fb[2][4][4];

    auto prefetch = [&](int buf, int s, int kk) {
        uint32_t ka = ((uint32_t)kk * 32 + cbA) ^ xorA;
        uint32_t kb = ((uint32_t)kk * 32 + cbB) ^ xorB;
        uint32_t aS = aRow + (uint32_t)s * STAGE_BYTES + ka;
        uint32_t bS = bRow + (uint32_t)s * STAGE_BYTES + kb;
        #pragma unroll
        for (int mi = 0; mi < 4; mi++)
            ldsm4(fa[buf][mi], aS + mi * (16 * 128));
        #pragma unroll
        for (int nj2 = 0; nj2 < 4; nj2++)
            ldsm4(fb[buf][nj2], bS + nj2 * (16 * 128));
    };

    // producer cursor (tid 0 only) and consumer full cursor (all threads)
    int estage = 0, ephase = 1;        // first empty-waits pass immediately
    int fstage = 0, fphase = 0;

    // ---- prologue: fill stages 0..2; wait full 0,1; prime (0,0) ----
    if (tid == 0) {
        #pragma unroll
        for (int s = 0; s < STAGES - 1; s++) {
            MBARRIER_WAIT_PARITY(sb + SM_EMPTY(estage), ephase);
            if (++estage == STAGES) { estage = 0; ephase ^= 1; }
            MBARRIER_EXPECT_TX(sb + SM_FULL(s), STAGE_BYTES);
            BULK_G2S(sb + SM_DATA + s * STAGE_BYTES,
                     __cvta_generic_to_global(aG + ((size_t)s << 14)),
                     A_BLK_BYTES, sb + SM_FULL(s));
            BULK_G2S(sb + SM_DATA + s * STAGE_BYTES + A_BLK_BYTES,
                     __cvta_generic_to_global(bG + ((size_t)s << 15)),
                     B_BLK_BYTES, sb + SM_FULL(s));
        }
    }
    MBARRIER_WAIT_PARITY(sb + SM_FULL(fstage), fphase);
    if (++fstage == STAGES) { fstage = 0; fphase ^= 1; }
    MBARRIER_WAIT_PARITY(sb + SM_FULL(fstage), fphase);
    if (++fstage == STAGES) { fstage = 0; fphase ^= 1; }
    prefetch(0, 0, 0);

    for (int kt = 0; kt < KT; kt++) {
        int s = kt & (STAGES - 1);
        int lt = kt + STAGES - 1;

        // producer: fill stage (kt+3)&3 (emptied at end of iteration kt-1)
        if (tid == 0 && lt < KT) {
            int ls = lt & (STAGES - 1);
            MBARRIER_WAIT_PARITY(sb + SM_EMPTY(estage), ephase);
            if (++estage == STAGES) { estage = 0; ephase ^= 1; }
            MBARRIER_EXPECT_TX(sb + SM_FULL(ls), STAGE_BYTES);
            BULK_G2S(sb + SM_DATA + ls * STAGE_BYTES,
                     __cvta_generic_to_global(aG + ((size_t)lt << 14)),
                     A_BLK_BYTES, sb + SM_FULL(ls));
            BULK_G2S(sb + SM_DATA + ls * STAGE_BYTES + A_BLK_BYTES,
                     __cvta_generic_to_global(bG + ((size_t)lt << 15)),
                     B_BLK_BYTES, sb + SM_FULL(ls));
        }

        #pragma unroll
        for (int kk = 0; kk < 4; kk++) {
            int cur = kk & 1, nxt = cur ^ 1;
            if (kk < 3)
                prefetch(nxt, s, kk + 1);
            else if (kt + 1 < KT)
                prefetch(nxt, (kt + 1) & (STAGES - 1), 0);   // stage kt+1 already waited
            #pragma unroll
            for (int mi = 0; mi < 4; mi++)
                #pragma unroll
                for (int nj = 0; nj < 8; nj++)
                    mma16816(acc[mi][nj], fa[cur][mi],
                             fb[cur][nj >> 1][(nj & 1) * 2],
                             fb[cur][nj >> 1][(nj & 1) * 2 + 1]);
        }

        // release stage kt (reads done), then wait stage kt+2 (needed at
        // iteration kt+1's kk=3 cross-stage prefetch)
        MBARRIER_ARRIVE(sb + SM_EMPTY(s));
        if (kt + 2 < KT) {
            MBARRIER_WAIT_PARITY(sb + SM_FULL(fstage), fphase);
            if (++fstage == STAGES) { fstage = 0; fphase ^= 1; }
        }
    }

    // ---- epilogue: + bias, fp32 stores ----
    float* outp = out + (size_t)(m_tile * BM) * N_TOTAL + (size_t)n_tile * BN;
    const float* biasp = bias + (size_t)n_tile * BN;
    #pragma unroll
    for (int mi = 0; mi < 4; mi++) {
        int r0 = m_off + mi * 16 + (lane >> 2);
        #pragma unroll
        for (int nj = 0; nj < 8; nj++) {
            int c0 = n_off + nj * 8 + (lane & 3) * 2;
            float2 bv = *(const float2*)(biasp + c0);
            float2 v0, v1;
            v0.x = acc[mi][nj][0] + bv.x;
            v0.y = acc[mi][nj][1] + bv.y;
            v1.x = acc[mi][nj][2] + bv.x;
            v1.y = acc[mi][nj][3] + bv.y;
            *(float2*)(outp + (size_t)r0 * N_TOTAL + c0) = v0;
            *(float2*)(outp + (size_t)(r0 + 8) * N_TOTAL + c0) = v1;
        }
    }
}

// ---------------------------------------------------------------------------
extern "C" void kernel_launch(void* const* d_in, const int* in_sizes, int n_in,
                              void* d_out, int out_size) {
    const float* x    = (const float*)d_in[0];
    const int*   qw   = (const int*)d_in[1];
    const float* sw   = (const float*)d_in[2];
    const float* bias = (const float*)d_in[3];
    float* out = (float*)d_out;

    prep_kernel<<<XB + WB, 256>>>(x, qw, sw);

    cudaFuncSetAttribute(qgl_gemm_kernel,
                         cudaFuncAttributeMaxDynamicSharedMemorySize, SMEM_TOTAL);
    qgl_gemm_kernel<<<TILES_M * TILES_N, 256, SMEM_TOTAL>>>(bias, out);
}

// round 7
// speedup vs baseline: 1.7876x; 1.0183x over previous
#include <cuda_runtime.h>
#include <cuda_fp16.h>
#include <cstdint>

// ---------------------------------------------------------------------------
// QGroupLinear: y = x @ (qw*sw)^T + bias   (fp32 in/out)
// mma.sync (HMMA) GEMM, fp16 dequant scratch (rel_err ~3e-4).
// R7: PERSISTENT kernel (152 CTAs, atomic tile scheduler). The cp.async.bulk
// + mbarrier ring runs continuously across tile boundaries, so prologue fill
// and epilogue exposure are paid once per CTA instead of once per tile.
// Early empty-release (after last stage read) gives the producer a head start.
// ---------------------------------------------------------------------------

#define M_TOTAL 4096
#define N_TOTAL 11008
#define K_TOTAL 4096

#define BM 128
#define BN 256
#define BK 64                       // halfs per k-chunk (128 B rows)
#define STAGES 4
#define KT (K_TOTAL / BK)           // 64  (divisible by STAGES -> tiles start at stage 0)
#define TILES_M (M_TOTAL / BM)      // 32
#define TILES_N (N_TOTAL / BN)      // 43
#define NTILES (TILES_M * TILES_N)  // 1376
#define GRID 152

#define A_BLK_BYTES (BM * 128)      // 16384
#define B_BLK_BYTES (BN * 128)      // 32768
#define STAGE_BYTES (A_BLK_BYTES + B_BLK_BYTES)   // 49152

// SMEM: [0..31] full mbarriers, [32..63] empty mbarriers, [64..79] tile queue
#define SM_FULL(s)  ((s) * 8)
#define SM_EMPTY(s) (32 + (s) * 8)
#define SM_TILEQ    64
#define SM_DATA     1024
#define SMEM_TOTAL  (SM_DATA + STAGES * STAGE_BYTES)   // 197632

// tiled + swizzled fp16 scratch (uint4 for 16B-aligned access)
__device__ uint4 d_X16T[2097152];   // 32 MB : block (m_tile*64+kc) = 16 KB
__device__ uint4 d_W16T[5636096];   // 90 MB : block (n_tile*64+kc) = 32 KB
__device__ int   g_tile_ctr;

// ---------------------------------------------------------------------------
__device__ __forceinline__ uint32_t smem_u32(const void* p) {
    uint32_t a;
    asm("{ .reg .u64 t; cvta.to.shared.u64 t, %1; cvt.u32.u64 %0, t; }"
        : "=r"(a) : "l"(p));
    return a;
}

#define MBARRIER_INIT(addr, cnt) \
    asm volatile("mbarrier.init.shared.b64 [%0], %1;" :: "r"((uint32_t)(addr)), "r"((uint32_t)(cnt)) : "memory")
#define MBARRIER_EXPECT_TX(addr, bytes) \
    asm volatile("mbarrier.arrive.expect_tx.shared.b64 _, [%0], %1;" :: "r"((uint32_t)(addr)), "r"((uint32_t)(bytes)) : "memory")
#define MBARRIER_ARRIVE(addr) \
    asm volatile("mbarrier.arrive.shared.b64 _, [%0];" :: "r"((uint32_t)(addr)) : "memory")
#define FENCE_PROXY_ASYNC() asm volatile("fence.proxy.async.shared::cta;" ::: "memory")

#define MBARRIER_WAIT_PARITY(mbar_smem_addr, phase_parity) do { \
    uint32_t _mbar = (uint32_t)(mbar_smem_addr); \
    uint32_t _parity = (uint32_t)(phase_parity); \
    uint32_t _done; \
    asm volatile( \
        "{\n\t.reg .pred p;\n\t" \
        "mbarrier.try_wait.parity.acquire.cta.shared::cta.b64 p, [%1], %2;\n\t" \
        "selp.b32 %0, 1, 0, p;\n\t}" \
        : "=r"(_done) : "r"(_mbar), "r"(_parity) : "memory"); \
    if (!_done) { \
        asm volatile( \
            "{\n\t.reg .pred P1;\n\t" \
            "WAIT_LOOP_%=:\n\t" \
            "mbarrier.try_wait.parity.acquire.cta.shared::cta.b64 P1, [%0], %1, 0x989680;\n\t" \
            "@P1 bra.uni WAIT_DONE_%=;\n\t" \
            "bra.uni WAIT_LOOP_%=;\n\t" \
            "WAIT_DONE_%=:\n\t}" \
            :: "r"(_mbar), "r"(_parity) : "memory"); \
    } \
} while (0)

#define BULK_G2S(dst, src, bytes, mbar) \
    asm volatile("cp.async.bulk.shared::cta.global.mbarrier::complete_tx::bytes [%0], [%1], %2, [%3];" \
        :: "r"((uint32_t)(dst)), "l"((unsigned long long)(src)), "r"((uint32_t)(bytes)), "r"((uint32_t)(mbar)) : "memory")

__device__ __forceinline__ void ldsm4(uint32_t* r, uint32_t addr) {
    asm volatile("ldmatrix.sync.aligned.m8n8.x4.shared.b16 {%0,%1,%2,%3}, [%4];"
                 : "=r"(r[0]), "=r"(r[1]), "=r"(r[2]), "=r"(r[3]) : "r"(addr));
}

__device__ __forceinline__ void mma16816(float* c, const uint32_t* a,
                                         uint32_t b0, uint32_t b1) {
    asm volatile(
        "mma.sync.aligned.m16n8k16.row.col.f32.f16.f16.f32 "
        "{%0,%1,%2,%3}, {%4,%5,%6,%7}, {%8,%9}, {%0,%1,%2,%3};"
        : "+f"(c[0]), "+f"(c[1]), "+f"(c[2]), "+f"(c[3])
        : "r"(a[0]), "r"(a[1]), "r"(a[2]), "r"(a[3]), "r"(b0), "r"(b1));
}

// ---------------------------------------------------------------------------
// Fused prep: tiled + SW128-swizzled fp16 blocks (8 halfs / 16 B per thread).
// Also resets the persistent-GEMM tile counter each launch.
// ---------------------------------------------------------------------------
#define XB ((M_TOTAL * K_TOTAL / 8) / 256)    // 8192 blocks
#define WB ((N_TOTAL * K_TOTAL / 8) / 256)    // 22016 blocks

__global__ void __launch_bounds__(256) prep_kernel(const float* __restrict__ x,
                                                   const int* __restrict__ qw,
                                                   const float* __restrict__ sw) {
    if (blockIdx.x == 0 && threadIdx.x == 0) g_tile_ctr = 0;
    int b = blockIdx.x;
    if (b < XB) {
        int idx = b * 256 + threadIdx.x;
        int m = idx >> 9;                     // 512 8-half chunks per row
        int k0 = (idx & 511) << 3;
        const float* src = x + (size_t)m * K_TOTAL + k0;
        float4 v0 = *(const float4*)src;
        float4 v1 = *(const float4*)(src + 4);
        __half2 h0 = __floats2half2_rn(v0.x, v0.y);
        __half2 h1 = __floats2half2_rn(v0.z, v0.w);
        __half2 h2 = __floats2half2_rn(v1.x, v1.y);
        __half2 h3 = __floats2half2_rn(v1.z, v1.w);
        uint4 pk;
        pk.x = *(uint32_t*)&h0; pk.y = *(uint32_t*)&h1;
        pk.z = *(uint32_t*)&h2; pk.w = *(uint32_t*)&h3;
        int blk = (m >> 7) * KT + (k0 >> 6);
        int row = m & 127, ch = k0 & 63;
        uint32_t off = (uint32_t)row * 128 + (((uint32_t)ch * 2) ^ (((uint32_t)(row & 7)) << 4));
        *(uint4*)((char*)d_X16T + (((size_t)blk) << 14) + off) = pk;
    } else {
        int idx = (b - XB) * 256 + threadIdx.x;
        int n = idx >> 9;
        int k0 = (idx & 511) << 3;
        const int* src = qw + (size_t)n * K_TOTAL + k0;
        int4 q0 = *(const int4*)src;
        int4 q1 = *(const int4*)(src + 4);
        float s = sw[n * 32 + (k0 >> 7)];
        __half2 h0 = __floats2half2_rn((float)q0.x * s, (float)q0.y * s);
        __half2 h1 = __floats2half2_rn((float)q0.z * s, (float)q0.w * s);
        __half2 h2 = __floats2half2_rn((float)q1.x * s, (float)q1.y * s);
        __half2 h3 = __floats2half2_rn((float)q1.z * s, (float)q1.w * s);
        uint4 pk;
        pk.x = *(uint32_t*)&h0; pk.y = *(uint32_t*)&h1;
        pk.z = *(uint32_t*)&h2; pk.w = *(uint32_t*)&h3;
        int blk = (n >> 8) * KT + (k0 >> 6);
        int row = n & 255, ch = k0 & 63;
        uint32_t off = (uint32_t)row * 128 + (((uint32_t)ch * 2) ^ (((uint32_t)(row & 7)) << 4));
        *(uint4*)((char*)d_W16T + (((size_t)blk) << 15) + off) = pk;
    }
}

// ---------------------------------------------------------------------------
// Persistent GEMM: 256 threads, 8 warps as 2(m) x 4(n), warp tile 64x64.
// Dynamic tile scheduler via atomicAdd; ring runs continuously across tiles.
// tile t: m_tile = t & 31, n_tile = t >> 5 (column-major for L2 locality).
// ---------------------------------------------------------------------------
__global__ void __launch_bounds__(256, 1) qgl_gemm_kernel(const float* __restrict__ bias,
                                                          float* __restrict__ out) {
    extern __shared__ char smem[];
    uint32_t sb = smem_u32(smem);
    int tid = threadIdx.x;
    int lane = tid & 31;
    int wid = tid >> 5;
    int warp_m = wid & 1;
    int warp_n = wid >> 1;
    int m_off = warp_m * 64;
    int n_off = warp_n * 64;

    int* tileq = (int*)(smem + SM_TILEQ);

    if (tid == 0) {
        #pragma unroll
        for (int s = 0; s < STAGES; s++) {
            MBARRIER_INIT(sb + SM_FULL(s), 1);
            MBARRIER_INIT(sb + SM_EMPTY(s), 256);
        }
        FENCE_PROXY_ASYNC();
        int t = atomicAdd(&g_tile_ctr, 1);
        tileq[0] = (t < NTILES) ? t : -1;
    }
    __syncthreads();

    // ldmatrix lane addressing with SW128 swizzle (stage 0 bases)
    int rowA = m_off + (lane & 15);
    uint32_t xorA = (uint32_t)(rowA & 7) << 4;
    uint32_t cbA = ((uint32_t)(lane >> 4)) << 4;
    uint32_t aRow = sb + SM_DATA + (uint32_t)rowA * 128;

    int rowB = n_off + ((lane & 7) | ((lane & 16) >> 1));
    uint32_t xorB = (uint32_t)(rowB & 7) << 4;
    uint32_t cbB = ((uint32_t)((lane >> 3) & 1)) << 4;
    uint32_t bRow = sb + SM_DATA + A_BLK_BYTES + (uint32_t)rowB * 128;

    float acc[4][8][4];
    #pragma unroll
    for (int mi = 0; mi < 4; mi++)
        #pragma unroll
        for (int nj = 0; nj < 8; nj++)
            #pragma unroll
            for (int r = 0; r < 4; r++) acc[mi][nj][r] = 0.0f;

    uint32_t fa[2][4][4], fb[2][4][4];

    auto prefetch = [&](int buf, int s, int kk) {
        uint32_t ka = ((uint32_t)kk * 32 + cbA) ^ xorA;
        uint32_t kb = ((uint32_t)kk * 32 + cbB) ^ xorB;
        uint32_t aS = aRow + (uint32_t)s * STAGE_BYTES + ka;
        uint32_t bS = bRow + (uint32_t)s * STAGE_BYTES + kb;
        #pragma unroll
        for (int mi = 0; mi < 4; mi++)
            ldsm4(fa[buf][mi], aS + mi * (16 * 128));
        #pragma unroll
        for (int nj2 = 0; nj2 < 4; nj2++)
            ldsm4(fb[buf][nj2], bS + nj2 * (16 * 128));
    };

    // producer cursor (tid0) and consumer full cursor (all threads)
    int estage = 0, ephase = 1;
    int fstage = 0, fphase = 0;
    int ti = 0;
    int cur = tileq[0];

    // ---- first-tile prologue: fill chunks 0..2 ----
    if (tid == 0 && cur >= 0) {
        const char* aG = (const char*)d_X16T + (((size_t)(cur & 31) * KT) << 14);
        const char* bG = (const char*)d_W16T + (((size_t)(cur >> 5) * KT) << 15);
        #pragma unroll
        for (int s = 0; s < STAGES - 1; s++) {
            MBARRIER_WAIT_PARITY(sb + SM_EMPTY(estage), ephase);
            if (++estage == STAGES) { estage = 0; ephase ^= 1; }
            MBARRIER_EXPECT_TX(sb + SM_FULL(s), STAGE_BYTES);
            BULK_G2S(sb + SM_DATA + s * STAGE_BYTES,
                     __cvta_generic_to_global(aG + ((size_t)s << 14)),
                     A_BLK_BYTES, sb + SM_FULL(s));
            BULK_G2S(sb + SM_DATA + s * STAGE_BYTES + A_BLK_BYTES,
                     __cvta_generic_to_global(bG + ((size_t)s << 15)),
                     B_BLK_BYTES, sb + SM_FULL(s));
        }
    }

    while (cur >= 0) {
        int m_tile = cur & (TILES_M - 1);
        int n_tile = cur >> 5;
        const char* aG = (const char*)d_X16T + (((size_t)m_tile * KT) << 14);
        const char* bG = (const char*)d_W16T + (((size_t)n_tile * KT) << 15);
        int next_tile = -1;  // tid0 only

        // tile entry: wait chunks 0,1 (always stages 0,1) and prime fragments
        MBARRIER_WAIT_PARITY(sb + SM_FULL(fstage), fphase);
        if (++fstage == STAGES) { fstage = 0; fphase ^= 1; }
        MBARRIER_WAIT_PARITY(sb + SM_FULL(fstage), fphase);
        if (++fstage == STAGES) { fstage = 0; fphase ^= 1; }
        prefetch(0, 0, 0);

        for (int kt = 0; kt < KT; kt++) {
            // ---- producer (tid0): fill chunk kt+3 (may belong to next tile) ----
            if (tid == 0) {
                if (kt == 0) {
                    int t = atomicAdd(&g_tile_ctr, 1);
                    next_tile = (t < NTILES) ? t : -1;
                    tileq[(ti + 1) & 3] = next_tile;
                }
                int lt = kt + STAGES - 1;
                const char *pa = nullptr, *pb = nullptr;
                bool fill = false;
                if (lt < KT) {
                    pa = aG + ((size_t)lt << 14);
                    pb = bG + ((size_t)lt << 15);
                    fill = true;
                } else if (next_tile >= 0) {
                    int nm = next_tile & (TILES_M - 1), nn = next_tile >> 5;
                    int l2 = lt - KT;
                    pa = (const char*)d_X16T + (((size_t)nm * KT + l2) << 14);
                    pb = (const char*)d_W16T + (((size_t)nn * KT + l2) << 15);
                    fill = true;
                }
                if (fill) {
                    int ls = lt & (STAGES - 1);
                    MBARRIER_WAIT_PARITY(sb + SM_EMPTY(estage), ephase);
                    if (++estage == STAGES) { estage = 0; ephase ^= 1; }
                    MBARRIER_EXPECT_TX(sb + SM_FULL(ls), STAGE_BYTES);
                    BULK_G2S(sb + SM_DATA + ls * STAGE_BYTES,
                             __cvta_generic_to_global(pa), A_BLK_BYTES, sb + SM_FULL(ls));
                    BULK_G2S(sb + SM_DATA + ls * STAGE_BYTES + A_BLK_BYTES,
                             __cvta_generic_to_global(pb), B_BLK_BYTES, sb + SM_FULL(ls));
                }
            }

            int s = kt & (STAGES - 1);
            #pragma unroll
            for (int kk = 0; kk < 4; kk++) {
                int curb = kk & 1, nxt = curb ^ 1;
                if (kk < 3)
                    prefetch(nxt, s, kk + 1);
                else if (kt + 1 < KT)
                    prefetch(nxt, (kt + 1) & (STAGES - 1), 0);
                // last read of stage s was the kk==2 prefetch -> release early
                if (kk == 2) MBARRIER_ARRIVE(sb + SM_EMPTY(s));
                #pragma unroll
                for (int mi = 0; mi < 4; mi++)
                    #pragma unroll
                    for (int nj = 0; nj < 8; nj++)
                        mma16816(acc[mi][nj], fa[curb][mi],
                                 fb[curb][nj >> 1][(nj & 1) * 2],
                                 fb[curb][nj >> 1][(nj & 1) * 2 + 1]);
            }

            // wait chunk kt+2 (needed at iteration kt+1's kk=3 prefetch)
            if (kt + 2 < KT) {
                MBARRIER_WAIT_PARITY(sb + SM_FULL(fstage), fphase);
                if (++fstage == STAGES) { fstage = 0; fphase ^= 1; }
            }
        }

        // ---- epilogue: + bias, fp32 stores; producer keeps 3 stages banked ----
        float* outp = out + (size_t)(m_tile * BM) * N_TOTAL + (size_t)n_tile * BN;
        const float* biasp = bias + (size_t)n_tile * BN;
        #pragma unroll
        for (int mi = 0; mi < 4; mi++) {
            int r0 = m_off + mi * 16 + (lane >> 2);
            #pragma unroll
            for (int nj = 0; nj < 8; nj++) {
                int c0 = n_off + nj * 8 + (lane & 3) * 2;
                float2 bv = *(const float2*)(biasp + c0);
                float2 v0, v1;
                v0.x = acc[mi][nj][0] + bv.x;
                v0.y = acc[mi][nj][1] + bv.y;
                v1.x = acc[mi][nj][2] + bv.x;
                v1.y = acc[mi][nj][3] + bv.y;
                *(float2*)(outp + (size_t)r0 * N_TOTAL + c0) = v0;
                *(float2*)(outp + (size_t)(r0 + 8) * N_TOTAL + c0) = v1;
                acc[mi][nj][0] = 0.0f; acc[mi][nj][1] = 0.0f;
                acc[mi][nj][2] = 0.0f; acc[mi][nj][3] = 0.0f;
            }
        }

        ti++;
        __syncthreads();          // publish tileq[ti&3] to all threads
        cur = tileq[ti & 3];
    }
}

// ---------------------------------------------------------------------------
extern "C" void kernel_launch(void* const* d_in, const int* in_sizes, int n_in,
                              void* d_out, int out_size) {
    const float* x    = (const float*)d_in[0];
    const int*   qw   = (const int*)d_in[1];
    const float* sw   = (const float*)d_in[2];
    const float* bias = (const float*)d_in[3];
    float* out = (float*)d_out;

    prep_kernel<<<XB + WB, 256>>>(x, qw, sw);

    cudaFuncSetAttribute(qgl_gemm_kernel,
                         cudaFuncAttributeMaxDynamicSharedMemorySize, SMEM_TOTAL);
    qgl_gemm_kernel<<<GRID, 256, SMEM_TOTAL>>>(bias, out);
}

// round 8
// speedup vs baseline: 1.9030x; 1.0646x over previous
#include <cuda_runtime.h>
#include <cuda_fp16.h>
#include <cstdint>

// ---------------------------------------------------------------------------
// QGroupLinear: y = x @ (qw*sw)^T + bias   (fp32 in/out)
// mma.sync (HMMA) GEMM, fp16 dequant scratch (rel_err ~3e-4).
// R8: tail-quantization fix. 1368 full 128x256 tiles = exactly 9 waves of 152
// CTAs; the 8 leftover tiles are split into 32 quarter-units (128x64, NJ=2)
// so the final partial round costs ~1/4 tile-time instead of a full tile.
// ---------------------------------------------------------------------------

#define M_TOTAL 4096
#define N_TOTAL 11008
#define K_TOTAL 4096

#define BM 128
#define BN 256
#define STAGES 4
#define KT (K_TOTAL / 64)           // 64 chunks of 64 halfs
#define TILES_M (M_TOTAL / BM)      // 32
#define TILES_N (N_TOTAL / BN)      // 43
#define NTILES (TILES_M * TILES_N)  // 1376
#define NFULL 1368                  // 152 * 9
#define NUNITS (NFULL + (NTILES - NFULL) * 4)   // 1400
#define GRID 152

#define A_BLK_BYTES (BM * 128)      // 16384
#define B_BLK_BYTES (BN * 128)      // 32768
#define STAGE_BYTES (A_BLK_BYTES + B_BLK_BYTES)   // 49152

#define SM_FULL(s)  ((s) * 8)
#define SM_EMPTY(s) (32 + (s) * 8)
#define SM_TILEQ    64
#define SM_DATA     1024
#define SMEM_TOTAL  (SM_DATA + STAGES * STAGE_BYTES)   // 197632

__device__ uint4 d_X16T[2097152];   // 32 MB : block (m_tile*64+kc) = 16 KB
__device__ uint4 d_W16T[5636096];   // 90 MB : block (n_tile*64+kc) = 32 KB
__device__ int   g_tile_ctr;

// ---------------------------------------------------------------------------
__device__ __forceinline__ uint32_t smem_u32(const void* p) {
    uint32_t a;
    asm("{ .reg .u64 t; cvta.to.shared.u64 t, %1; cvt.u32.u64 %0, t; }"
        : "=r"(a) : "l"(p));
    return a;
}

#define MBARRIER_INIT(addr, cnt) \
    asm volatile("mbarrier.init.shared.b64 [%0], %1;" :: "r"((uint32_t)(addr)), "r"((uint32_t)(cnt)) : "memory")
#define MBARRIER_EXPECT_TX(addr, bytes) \
    asm volatile("mbarrier.arrive.expect_tx.shared.b64 _, [%0], %1;" :: "r"((uint32_t)(addr)), "r"((uint32_t)(bytes)) : "memory")
#define MBARRIER_ARRIVE(addr) \
    asm volatile("mbarrier.arrive.shared.b64 _, [%0];" :: "r"((uint32_t)(addr)) : "memory")
#define FENCE_PROXY_ASYNC() asm volatile("fence.proxy.async.shared::cta;" ::: "memory")

#define MBARRIER_WAIT_PARITY(mbar_smem_addr, phase_parity) do { \
    uint32_t _mbar = (uint32_t)(mbar_smem_addr); \
    uint32_t _parity = (uint32_t)(phase_parity); \
    uint32_t _done; \
    asm volatile( \
        "{\n\t.reg .pred p;\n\t" \
        "mbarrier.try_wait.parity.acquire.cta.shared::cta.b64 p, [%1], %2;\n\t" \
        "selp.b32 %0, 1, 0, p;\n\t}" \
        : "=r"(_done) : "r"(_mbar), "r"(_parity) : "memory"); \
    if (!_done) { \
        asm volatile( \
            "{\n\t.reg .pred P1;\n\t" \
            "WAIT_LOOP_%=:\n\t" \
            "mbarrier.try_wait.parity.acquire.cta.shared::cta.b64 P1, [%0], %1, 0x989680;\n\t" \
            "@P1 bra.uni WAIT_DONE_%=;\n\t" \
            "bra.uni WAIT_LOOP_%=;\n\t" \
            "WAIT_DONE_%=:\n\t}" \
            :: "r"(_mbar), "r"(_parity) : "memory"); \
    } \
} while (0)

#define BULK_G2S(dst, src, bytes, mbar) \
    asm volatile("cp.async.bulk.shared::cta.global.mbarrier::complete_tx::bytes [%0], [%1], %2, [%3];" \
        :: "r"((uint32_t)(dst)), "l"((unsigned long long)(src)), "r"((uint32_t)(bytes)), "r"((uint32_t)(mbar)) : "memory")

__device__ __forceinline__ void ldsm4(uint32_t* r, uint32_t addr) {
    asm volatile("ldmatrix.sync.aligned.m8n8.x4.shared.b16 {%0,%1,%2,%3}, [%4];"
                 : "=r"(r[0]), "=r"(r[1]), "=r"(r[2]), "=r"(r[3]) : "r"(addr));
}

__device__ __forceinline__ void mma16816(float* c, const uint32_t* a,
                                         uint32_t b0, uint32_t b1) {
    asm volatile(
        "mma.sync.aligned.m16n8k16.row.col.f32.f16.f16.f32 "
        "{%0,%1,%2,%3}, {%4,%5,%6,%7}, {%8,%9}, {%0,%1,%2,%3};"
        : "+f"(c[0]), "+f"(c[1]), "+f"(c[2]), "+f"(c[3])
        : "r"(a[0]), "r"(a[1]), "r"(a[2]), "r"(a[3]), "r"(b0), "r"(b1));
}

// unit decode: u < NFULL -> full tile; else quarter slice of tiles 1368..1375
__device__ __forceinline__ void decode_unit(int u, int& mt, int& nt, int& nlo) {
    if (u < NFULL) {
        mt = u & (TILES_M - 1); nt = u >> 5; nlo = 0;
    } else {
        int v = u - NFULL;
        int t = NFULL + (v >> 2);
        mt = t & (TILES_M - 1); nt = t >> 5; nlo = (v & 3) * 64;
    }
}

__device__ __forceinline__ void fill_chunk(uint32_t sb, int s,
                                           const char* aG, const char* bG,
                                           int chunk, uint32_t bbytes,
                                           int& estage, int& ephase) {
    MBARRIER_WAIT_PARITY(sb + SM_EMPTY(estage), ephase);
    if (++estage == STAGES) { estage = 0; ephase ^= 1; }
    MBARRIER_EXPECT_TX(sb + SM_FULL(s), A_BLK_BYTES + bbytes);
    BULK_G2S(sb + SM_DATA + s * STAGE_BYTES,
             __cvta_generic_to_global(aG + ((size_t)chunk << 14)),
             A_BLK_BYTES, sb + SM_FULL(s));
    BULK_G2S(sb + SM_DATA + s * STAGE_BYTES + A_BLK_BYTES,
             __cvta_generic_to_global(bG + ((size_t)chunk << 15)),
             bbytes, sb + SM_FULL(s));
}

// ---------------------------------------------------------------------------
// Fused prep: tiled + SW128-swizzled fp16 blocks; resets tile counter.
// ---------------------------------------------------------------------------
#define XB ((M_TOTAL * K_TOTAL / 8) / 256)    // 8192 blocks
#define WB ((N_TOTAL * K_TOTAL / 8) / 256)    // 22016 blocks

__global__ void __launch_bounds__(256) prep_kernel(const float* __restrict__ x,
                                                   const int* __restrict__ qw,
                                                   const float* __restrict__ sw) {
    if (blockIdx.x == 0 && threadIdx.x == 0) g_tile_ctr = 0;
    int b = blockIdx.x;
    if (b < XB) {
        int idx = b * 256 + threadIdx.x;
        int m = idx >> 9;
        int k0 = (idx & 511) << 3;
        const float* src = x + (size_t)m * K_TOTAL + k0;
        float4 v0 = *(const float4*)src;
        float4 v1 = *(const float4*)(src + 4);
        __half2 h0 = __floats2half2_rn(v0.x, v0.y);
        __half2 h1 = __floats2half2_rn(v0.z, v0.w);
        __half2 h2 = __floats2half2_rn(v1.x, v1.y);
        __half2 h3 = __floats2half2_rn(v1.z, v1.w);
        uint4 pk;
        pk.x = *(uint32_t*)&h0; pk.y = *(uint32_t*)&h1;
        pk.z = *(uint32_t*)&h2; pk.w = *(uint32_t*)&h3;
        int blk = (m >> 7) * KT + (k0 >> 6);
        int row = m & 127, ch = k0 & 63;
        uint32_t off = (uint32_t)row * 128 + (((uint32_t)ch * 2) ^ (((uint32_t)(row & 7)) << 4));
        *(uint4*)((char*)d_X16T + (((size_t)blk) << 14) + off) = pk;
    } else {
        int idx = (b - XB) * 256 + threadIdx.x;
        int n = idx >> 9;
        int k0 = (idx & 511) << 3;
        const int* src = qw + (size_t)n * K_TOTAL + k0;
        int4 q0 = *(const int4*)src;
        int4 q1 = *(const int4*)(src + 4);
        float s = sw[n * 32 + (k0 >> 7)];
        __half2 h0 = __floats2half2_rn((float)q0.x * s, (float)q0.y * s);
        __half2 h1 = __floats2half2_rn((float)q0.z * s, (float)q0.w * s);
        __half2 h2 = __floats2half2_rn((float)q1.x * s, (float)q1.y * s);
        __half2 h3 = __floats2half2_rn((float)q1.z * s, (float)q1.w * s);
        uint4 pk;
        pk.x = *(uint32_t*)&h0; pk.y = *(uint32_t*)&h1;
        pk.z = *(uint32_t*)&h2; pk.w = *(uint32_t*)&h3;
        int blk = (n >> 8) * KT + (k0 >> 6);
        int row = n & 255, ch = k0 & 63;
        uint32_t off = (uint32_t)row * 128 + (((uint32_t)ch * 2) ^ (((uint32_t)(row & 7)) << 4));
        *(uint4*)((char*)d_W16T + (((size_t)blk) << 15) + off) = pk;
    }
}

// ---------------------------------------------------------------------------
// Templated per-unit mainloop. NJ = 8 (full 128x256) or 2 (quarter 128x64).
// ---------------------------------------------------------------------------
template <int NJ>
__device__ __forceinline__ void run_unit(uint32_t sb, int tid, int lane, int wid,
                                         int cur_unit, int ti, int* tileq,
                                         int& estage, int& ephase,
                                         int& fstage, int& fphase,
                                         const float* __restrict__ bias,
                                         float* __restrict__ out) {
    int warp_m = wid & 1;
    int warp_n = wid >> 1;
    int m_off = warp_m * 64;
    int n_off = warp_n * (NJ * 8);

    int m_tile, n_tile, n_lo;
    decode_unit(cur_unit, m_tile, n_tile, n_lo);

    const char* aG = (const char*)d_X16T + (((size_t)m_tile * KT) << 14);
    const char* bG = (const char*)d_W16T + (((size_t)n_tile * KT) << 15) + (size_t)n_lo * 128;
    const uint32_t bbytes = NJ * 4096;

    // ldmatrix lane addressing with SW128 swizzle (stage 0 bases)
    int rowA = m_off + (lane & 15);
    uint32_t xorA = (uint32_t)(rowA & 7) << 4;
    uint32_t cbA = ((uint32_t)(lane >> 4)) << 4;
    uint32_t aRow = sb + SM_DATA + (uint32_t)rowA * 128;

    int rowB = n_off + ((lane & 7) | ((lane & 16) >> 1));
    uint32_t xorB = (uint32_t)(rowB & 7) << 4;
    uint32_t cbB = ((uint32_t)((lane >> 3) & 1)) << 4;
    uint32_t bRow = sb + SM_DATA + A_BLK_BYTES + (uint32_t)rowB * 128;

    float acc[4][NJ][4];
    #pragma unroll
    for (int mi = 0; mi < 4; mi++)
        #pragma unroll
        for (int nj = 0; nj < NJ; nj++)
            #pragma unroll
            for (int r = 0; r < 4; r++) acc[mi][nj][r] = 0.0f;

    uint32_t fa[2][4][4], fb[2][NJ / 2][4];

    auto prefetch = [&](int buf, int s, int kk) {
        uint32_t ka = ((uint32_t)kk * 32 + cbA) ^ xorA;
        uint32_t kb = ((uint32_t)kk * 32 + cbB) ^ xorB;
        uint32_t aS = aRow + (uint32_t)s * STAGE_BYTES + ka;
        uint32_t bS = bRow + (uint32_t)s * STAGE_BYTES + kb;
        #pragma unroll
        for (int mi = 0; mi < 4; mi++)
            ldsm4(fa[buf][mi], aS + mi * (16 * 128));
        #pragma unroll
        for (int nj2 = 0; nj2 < NJ / 2; nj2++)
            ldsm4(fb[buf][nj2], bS + nj2 * (16 * 128));
    };

    int next_unit = -1;   // tid0 only

    // unit entry: wait chunks 0,1 and prime fragments
    MBARRIER_WAIT_PARITY(sb + SM_FULL(fstage), fphase);
    if (++fstage == STAGES) { fstage = 0; fphase ^= 1; }
    MBARRIER_WAIT_PARITY(sb + SM_FULL(fstage), fphase);
    if (++fstage == STAGES) { fstage = 0; fphase ^= 1; }
    prefetch(0, 0, 0);

    for (int kt = 0; kt < KT; kt++) {
        // ---- producer (tid0): fill chunk kt+3 (may spill into next unit) ----
        if (tid == 0) {
            if (kt == 0) {
                int t = atomicAdd(&g_tile_ctr, 1);
                next_unit = (t < NUNITS) ? t : -1;
                tileq[(ti + 1) & 3] = next_unit;
            }
            int lt = kt + STAGES - 1;
            if (lt < KT) {
                fill_chunk(sb, lt & (STAGES - 1), aG, bG, lt, bbytes, estage, ephase);
            } else if (next_unit >= 0) {
                int nm, nn, nl;
                decode_unit(next_unit, nm, nn, nl);
                const char* pa = (const char*)d_X16T + (((size_t)nm * KT) << 14);
                const char* pb = (const char*)d_W16T + (((size_t)nn * KT) << 15) + (size_t)nl * 128;
                uint32_t nb = (next_unit < NFULL) ? 32768u : 8192u;
                fill_chunk(sb, lt & (STAGES - 1), pa, pb, lt - KT, nb, estage, ephase);
            }
        }

        int s = kt & (STAGES - 1);
        #pragma unroll
        for (int kk = 0; kk < 4; kk++) {
            int curb = kk & 1, nxt = curb ^ 1;
            if (kk < 3)
                prefetch(nxt, s, kk + 1);
            else if (kt + 1 < KT)
                prefetch(nxt, (kt + 1) & (STAGES - 1), 0);
            if (kk == 2) MBARRIER_ARRIVE(sb + SM_EMPTY(s));   // last stage-s read done
            #pragma unroll
            for (int mi = 0; mi < 4; mi++)
                #pragma unroll
                for (int nj = 0; nj < NJ; nj++)
                    mma16816(acc[mi][nj], fa[curb][mi],
                             fb[curb][nj >> 1][(nj & 1) * 2],
                             fb[curb][nj >> 1][(nj & 1) * 2 + 1]);
        }

        // wait chunk kt+2 (needed at iteration kt+1's kk=3 prefetch)
        if (kt + 2 < KT) {
            MBARRIER_WAIT_PARITY(sb + SM_FULL(fstage), fphase);
            if (++fstage == STAGES) { fstage = 0; fphase ^= 1; }
        }
    }

    // ---- epilogue ----
    float* outp = out + (size_t)(m_tile * BM) * N_TOTAL + (size_t)n_tile * BN + n_lo;
    const float* biasp = bias + (size_t)n_tile * BN + n_lo;
    #pragma unroll
    for (int mi = 0; mi < 4; mi++) {
        int r0 = m_off + mi * 16 + (lane >> 2);
        #pragma unroll
        for (int nj = 0; nj < NJ; nj++) {
            int c0 = n_off + nj * 8 + (lane & 3) * 2;
            float2 bv = *(const float2*)(biasp + c0);
            float2 v0, v1;
            v0.x = acc[mi][nj][0] + bv.x;
            v0.y = acc[mi][nj][1] + bv.y;
            v1.x = acc[mi][nj][2] + bv.x;
            v1.y = acc[mi][nj][3] + bv.y;
            *(float2*)(outp + (size_t)r0 * N_TOTAL + c0) = v0;
            *(float2*)(outp + (size_t)(r0 + 8) * N_TOTAL + c0) = v1;
        }
    }
}

// ---------------------------------------------------------------------------
// Persistent GEMM driver.
// ---------------------------------------------------------------------------
__global__ void __launch_bounds__(256, 1) qgl_gemm_kernel(const float* __restrict__ bias,
                                                          float* __restrict__ out) {
    extern __shared__ char smem[];
    uint32_t sb = smem_u32(smem);
    int tid = threadIdx.x;
    int lane = tid & 31;
    int wid = tid >> 5;

    int* tileq = (int*)(smem + SM_TILEQ);

    if (tid == 0) {
        #pragma unroll
        for (int s = 0; s < STAGES; s++) {
            MBARRIER_INIT(sb + SM_FULL(s), 1);
            MBARRIER_INIT(sb + SM_EMPTY(s), 256);
        }
        FENCE_PROXY_ASYNC();
        int t = atomicAdd(&g_tile_ctr, 1);
        tileq[0] = (t < NUNITS) ? t : -1;
    }
    __syncthreads();

    int estage = 0, ephase = 1;
    int fstage = 0, fphase = 0;
    int ti = 0;
    int cur = tileq[0];

    // first-unit prologue: fill chunks 0..2
    if (tid == 0 && cur >= 0) {
        int mt, nt, nl;
        decode_unit(cur, mt, nt, nl);
        const char* aG = (const char*)d_X16T + (((size_t)mt * KT) << 14);
        const char* bG = (const char*)d_W16T + (((size_t)nt * KT) << 15) + (size_t)nl * 128;
        uint32_t bb = (cur < NFULL) ? 32768u : 8192u;
        #pragma unroll
        for (int s = 0; s < STAGES - 1; s++)
            fill_chunk(sb, s, aG, bG, s, bb, estage, ephase);
    }

    while (cur >= 0) {
        if (cur < NFULL)
            run_unit<8>(sb, tid, lane, wid, cur, ti, tileq,
                        estage, ephase, fstage, fphase, bias, out);
        else
            run_unit<2>(sb, tid, lane, wid, cur, ti, tileq,
                        estage, ephase, fstage, fphase, bias, out);
        ti++;
        __syncthreads();
        cur = tileq[ti & 3];
    }
}

// ---------------------------------------------------------------------------
extern "C" void kernel_launch(void* const* d_in, const int* in_sizes, int n_in,
                              void* d_out, int out_size) {
    const float* x    = (const float*)d_in[0];
    const int*   qw   = (const int*)d_in[1];
    const float* sw   = (const float*)d_in[2];
    const float* bias = (const float*)d_in[3];
    float* out = (float*)d_out;

    prep_kernel<<<XB + WB, 256>>>(x, qw, sw);

    cudaFuncSetAttribute(qgl_gemm_kernel,
                         cudaFuncAttributeMaxDynamicSharedMemorySize, SMEM_TOTAL);
    qgl_gemm_kernel<<<GRID, 256, SMEM_TOTAL>>>(bias, out);
}